// round 13
// baseline (speedup 1.0000x reference)
#include <cuda_runtime.h>
#include <cuda_fp16.h>
#include <cstdint>

#define HW    4096
#define NB    4
#define LOG2E 1.44269504088896340736f

// ---------------- scratch (device globals: allocation-free) ----------------
__device__ __half g_Qf[NB * HW * 64];   // [b][n][c] fp16, pre-scaled by log2e
__device__ __half g_Kf[NB * HW * 64];   // [b][n][c] fp16
__device__ __half g_Vf[NB * 64 * HW];   // [b][c][m] fp16 (w folded in)
__device__ float  g_w [NB * HW];        // w[m] = 1 + beta*edge

// ---------------- f32x2 packed-FMA helpers ----------------
__device__ __forceinline__ double dup2(float x) {
    double r; asm("mov.b64 %0, {%1,%1};" : "=d"(r) : "f"(x)); return r;
}
__device__ __forceinline__ void ffma2(double &d, double a, double b) {
    asm("fma.rn.f32x2 %0, %1, %2, %0;" : "+d"(d) : "d"(a), "d"(b));
}
__device__ __forceinline__ void unpack2(double v, float &lo, float &hi) {
    asm("mov.b64 {%0,%1}, %2;" : "=f"(lo), "=f"(hi) : "d"(v));
}
__device__ __forceinline__ float ex2f(float x) {
    float r; asm("ex2.approx.f32 %0, %1;" : "=f"(r) : "f"(x)); return r;
}
__device__ __forceinline__ uint32_t f16x2_pack(float lo, float hi) {
    uint32_t r; asm("cvt.rn.f16x2.f32 %0, %1, %2;" : "=r"(r) : "f"(hi), "f"(lo));
    return r;
}
__device__ __forceinline__ uint32_t ex2_h2(uint32_t h2) {
    asm("ex2.approx.f16x2 %0, %0;" : "+r"(h2));
    return h2;
}
__device__ __forceinline__ uint32_t movm_trans(uint32_t a) {
    uint32_t d;
    asm("movmatrix.sync.aligned.m8n8.trans.b16 %0, %1;" : "=r"(d) : "r"(a));
    return d;
}
__device__ __forceinline__ uint32_t smem_u32(const void* p) {
    uint32_t a;
    asm("{ .reg .u64 t; cvta.to.shared.u64 t, %1; cvt.u32.u64 %0, t; }"
        : "=r"(a) : "l"(p));
    return a;
}

#define SW128(o) ((o) ^ (((o) >> 3) & 0x70))
#define SWX(o)   ((o) ^ (((o) >> 4) & 0x70))   // for 256-byte rows

// ---------------- mma.sync / ldmatrix (fp16) ----------------
#define LDMX4(r, addr) \
    asm volatile("ldmatrix.sync.aligned.m8n8.x4.shared.b16 {%0,%1,%2,%3}, [%4];" \
        : "=r"((r)[0]), "=r"((r)[1]), "=r"((r)[2]), "=r"((r)[3]) : "r"(addr))

#define LDMX4T(r, addr) \
    asm volatile("ldmatrix.sync.aligned.m8n8.x4.trans.shared.b16 {%0,%1,%2,%3}, [%4];" \
        : "=r"((r)[0]), "=r"((r)[1]), "=r"((r)[2]), "=r"((r)[3]) : "r"(addr))

#define MMA16816(d, a, b0, b1) \
    asm volatile("mma.sync.aligned.m16n8k16.row.col.f32.f16.f16.f32 " \
        "{%0,%1,%2,%3},{%4,%5,%6,%7},{%8,%9},{%0,%1,%2,%3};" \
        : "+f"((d)[0]), "+f"((d)[1]), "+f"((d)[2]), "+f"((d)[3]) \
        : "r"((a)[0]), "r"((a)[1]), "r"((a)[2]), "r"((a)[3]), "r"(b0), "r"(b1))

// ================= kernel 1: edge detector -> g_w =================
// 128 CTAs; each CTA: 2 image rows (128 px), 512 thr.
// Channel split ACROSS WARP GROUPS: warps [0-3]=cu0 ... [12-15]=cu3, so all
// weight LDS stay warp-uniform broadcasts. cu1..3 park partials in smem.
#define XT_FLOATS (64 * 4 * 66)                 // 16896
#define WS_FLOATS (64 * 9 * 32)                 // 18432
#define RED_STRIDE 34
#define RED_FLOATS (3 * 128 * RED_STRIDE)       // 13056
#define EDGE_SMEM ((XT_FLOATS + WS_FLOATS + RED_FLOATS) * 4)   // 193536 B

__global__ __launch_bounds__(512) void edge_kernel(
    const float* __restrict__ x,  const float* __restrict__ We1,
    const float* __restrict__ be1,
    const float* __restrict__ bn_w, const float* __restrict__ bn_b,
    const float* __restrict__ bn_mean, const float* __restrict__ bn_var,
    const float* __restrict__ We2, const float* __restrict__ be2,
    const float* __restrict__ beta)
{
    extern __shared__ float es[];
    float* xt  = es;                         // [64ch][4r][66c]
    float* Wsh = es + XT_FLOATS;             // [(cc*9+k)*32 + ch]
    float* red = es + XT_FLOATS + WS_FLOATS; // [3][128px][34]
    __shared__ float s_sc[32], s_sh[32], s_w2[32];

    const int tid = threadIdx.x;
    const int b   = blockIdx.y;
    const int pr0 = blockIdx.x * 2;          // image row base (2 rows per CTA)

    if (tid < 32) {
        float s = bn_w[tid] * rsqrtf(bn_var[tid] + 1e-5f);
        s_sc[tid] = s;
        s_sh[tid] = (be1[tid] - bn_mean[tid]) * s + bn_b[tid];
        s_w2[tid] = We2[tid];
    }

    for (int e = tid; e < WS_FLOATS; e += 512) {
        int ch = e & 31, rest = e >> 5;
        int k = rest % 9, cc = rest / 9;
        Wsh[e] = We1[(ch * 64 + cc) * 9 + k];
    }
    for (int e = tid; e < XT_FLOATS; e += 512) {
        int c66 = e % 66, rest = e / 66;
        int r = rest & 3, ch = rest >> 2;
        int ir = pr0 - 1 + r, ic = c66 - 1;
        float v = 0.f;
        if (ir >= 0 && ir < 64 && ic >= 0 && ic < 64)
            v = x[(size_t)(b * 64 + ch) * HW + ir * 64 + ic];
        xt[e] = v;
    }
    __syncthreads();

    const int wid  = tid >> 5, lane = tid & 31;
    const int cu   = wid >> 2;               // channel quadrant 0..3 (16 ch)
    const int px   = (wid & 3) * 32 + lane;  // pixel 0..127
    const int pr   = px >> 6, col = px & 63;

    double acc2[16];
    #pragma unroll
    for (int i = 0; i < 16; i++) acc2[i] = 0.0;

    for (int ccl = 0; ccl < 16; ccl++) {
        const int cc = cu * 16 + ccl;
        const float* xb = &xt[(cc * 4 + pr) * 66 + col];
        float xv[9];
        #pragma unroll
        for (int ry = 0; ry < 3; ry++)
            #pragma unroll
            for (int rx = 0; rx < 3; rx++)
                xv[ry * 3 + rx] = xb[ry * 66 + rx];
        #pragma unroll
        for (int k = 0; k < 9; k++) {
            double dv = dup2(xv[k]);
            const double2* wrow = (const double2*)&Wsh[(cc * 9 + k) * 32];
            #pragma unroll
            for (int c4 = 0; c4 < 8; c4++) {
                const double2 w2 = wrow[c4];
                ffma2(acc2[2 * c4],     dv, w2.x);
                ffma2(acc2[2 * c4 + 1], dv, w2.y);
            }
        }
    }

    if (cu != 0) {
        double* rp = (double*)&red[((cu - 1) * 128 + px) * RED_STRIDE];
        #pragma unroll
        for (int i = 0; i < 16; i++) rp[i] = acc2[i];
    }
    __syncthreads();
    if (cu == 0) {
        const double* rp1 = (const double*)&red[(px)       * RED_STRIDE];
        const double* rp2 = (const double*)&red[(128 + px) * RED_STRIDE];
        const double* rp3 = (const double*)&red[(256 + px) * RED_STRIDE];
        float e2 = be2[0];
        #pragma unroll
        for (int c2 = 0; c2 < 16; c2++) {
            float a0, a1, p0, p1;
            unpack2(acc2[c2], a0, a1);
            unpack2(rp1[c2], p0, p1); a0 += p0; a1 += p1;
            unpack2(rp2[c2], p0, p1); a0 += p0; a1 += p1;
            unpack2(rp3[c2], p0, p1); a0 += p0; a1 += p1;
            const int ch = c2 * 2;
            float r0 = fmaxf(a0 * s_sc[ch]     + s_sh[ch],     0.f);
            float r1 = fmaxf(a1 * s_sc[ch + 1] + s_sh[ch + 1], 0.f);
            e2 += s_w2[ch] * r0 + s_w2[ch + 1] * r1;
        }
        float sig = 1.f / (1.f + ex2f(-e2 * LOG2E));
        g_w[b * HW + pr0 * 64 + px] = 1.f + beta[0] * sig;
    }
}

// ================= kernel 2: QKV via HMMA (R12 proven) =================
__global__ __launch_bounds__(384) void qkv_kernel(
    const float* __restrict__ x,
    const float* __restrict__ Wq, const float* __restrict__ bq,
    const float* __restrict__ Wk, const float* __restrict__ bk,
    const float* __restrict__ Wv, const float* __restrict__ bv)
{
    __shared__ __align__(16) __half Wf[192 * 64];   // SW128, 128B rows
    __shared__ __align__(16) __half xB[64 * 128];   // SWX, 256B rows [c][n]
    __shared__ float sb[192];
    __shared__ float wvs[128];

    const int tid = threadIdx.x;
    const int b   = blockIdx.y;
    const int n0  = blockIdx.x * 128;
    const uint32_t wf_b = smem_u32(Wf);
    const uint32_t xb_b = smem_u32(xB);

    for (int e = tid; e < 1536; e += 384) {
        int oc = e >> 3, chv = e & 7;
        const float* wsrc;
        float scale = 1.f;
        if (oc < 64)       { wsrc = Wq + oc * 64;        scale = LOG2E; }
        else if (oc < 128) { wsrc = Wk + (oc - 64) * 64; }
        else               { wsrc = Wv + (oc - 128) * 64; }
        const float4 f0 = *(const float4*)(wsrc + chv * 8);
        const float4 f1 = *(const float4*)(wsrc + chv * 8 + 4);
        __half2 h[4];
        h[0] = __floats2half2_rn(f0.x * scale, f0.y * scale);
        h[1] = __floats2half2_rn(f0.z * scale, f0.w * scale);
        h[2] = __floats2half2_rn(f1.x * scale, f1.y * scale);
        h[3] = __floats2half2_rn(f1.z * scale, f1.w * scale);
        *(uint4*)((char*)Wf + SW128(oc * 128 + chv * 16)) = *(uint4*)h;
    }
    for (int e = tid; e < 1024; e += 384) {
        int c = e >> 4, ch = e & 15;
        const float* xp = x + (size_t)(b * 64 + c) * HW + n0 + ch * 8;
        const float4 f0 = *(const float4*)xp;
        const float4 f1 = *(const float4*)(xp + 4);
        __half2 h[4];
        h[0] = __floats2half2_rn(f0.x, f0.y);
        h[1] = __floats2half2_rn(f0.z, f0.w);
        h[2] = __floats2half2_rn(f1.x, f1.y);
        h[3] = __floats2half2_rn(f1.z, f1.w);
        *(uint4*)((char*)xB + SWX(c * 256 + ch * 16)) = *(uint4*)h;
    }
    if (tid < 192)
        sb[tid] = (tid < 64) ? bq[tid] * LOG2E
                 : (tid < 128) ? bk[tid - 64] : bv[tid - 128];
    if (tid < 128) wvs[tid] = g_w[b * HW + n0 + tid];
    __syncthreads();

    const int wid  = tid >> 5, lane = tid & 31;
    const int g    = lane >> 2, u = lane & 3;
    const int mt   = wid;
    const int oc_b = mt * 16;

    uint32_t aW[4][4];
    #pragma unroll
    for (int ks = 0; ks < 4; ks++)
        LDMX4(aW[ks], wf_b + SW128((oc_b + (lane & 15)) * 128 +
                                   ks * 32 + (lane >> 4) * 16));

    float s[16][4];
    #pragma unroll
    for (int i = 0; i < 16; i++)
        s[i][0] = s[i][1] = s[i][2] = s[i][3] = 0.f;

    #pragma unroll
    for (int nt2 = 0; nt2 < 8; nt2++) {
        #pragma unroll
        for (int ks = 0; ks < 4; ks++) {
            uint32_t bb[4];
            LDMX4T(bb, xb_b + SWX((ks * 16 + (lane & 15)) * 256 +
                                  nt2 * 32 + (lane >> 4) * 16));
            MMA16816(s[2 * nt2],     aW[ks], bb[0], bb[1]);
            MMA16816(s[2 * nt2 + 1], aW[ks], bb[2], bb[3]);
        }
    }

    const float b0 = sb[oc_b + g], b1 = sb[oc_b + 8 + g];
    const bool isV = (mt >= 8);
    #pragma unroll
    for (int nt = 0; nt < 16; nt++) {
        const int nn = nt * 8 + 2 * u;
        float v00 = s[nt][0] + b0, v01 = s[nt][1] + b0;
        float v10 = s[nt][2] + b1, v11 = s[nt][3] + b1;
        if (isV) {
            const float w0 = wvs[nn], w1 = wvs[nn + 1];
            v00 *= w0; v01 *= w1; v10 *= w0; v11 *= w1;
        }
        uint32_t h0 = f16x2_pack(v00, v01);
        uint32_t h1 = f16x2_pack(v10, v11);
        if (isV) {
            const size_t vb = (size_t)(b * 64 + (oc_b - 128) + g) * HW + n0 + nn;
            *(uint32_t*)(g_Vf + vb)          = h0;
            *(uint32_t*)(g_Vf + vb + 8 * HW) = h1;
        } else {
            uint32_t t0 = movm_trans(h0);
            uint32_t t1 = movm_trans(h1);
            const int n = nt * 8 + g;
            __half* dst = (mt < 4) ? g_Qf : g_Kf;
            const int cb = (mt < 4) ? oc_b : oc_b - 64;
            const size_t qb = (size_t)(b * HW + n0 + n) * 64 + cb + 2 * u;
            *(uint32_t*)(dst + qb)     = t0;
            *(uint32_t*)(dst + qb + 8) = t1;
        }
    }
}

// ================= kernel 3: fp16 flash attention (R11 proven) ============
#define OFF_QF 0
#define OFF_K  16384
#define OFF_V  49152
#define OFF_AW 81920
#define SMEM_BYTES 82944
#define OFF_OST0 0
#define OFF_OST1 32768
#define OFF_MSH  65536
#define OFF_DSH  66560

__global__ __launch_bounds__(512, 1) void flash_kernel(
    const float* __restrict__ x, const float* __restrict__ gamma,
    float* __restrict__ out)
{
    extern __shared__ char smem[];
    const uint32_t sbase = smem_u32(smem);
    const int tid  = threadIdx.x;
    const int lane = tid & 31, wid = tid >> 5;
    const int qg   = wid & 7;
    const int half = wid >> 3;
    const int g    = lane >> 2;
    const int u    = lane & 3;
    const int q0w  = qg * 16;
    const int b    = blockIdx.y;
    const int n0   = blockIdx.x * 128;

    {
        const uint4* Qg = (const uint4*)(g_Qf + ((size_t)(b * HW + n0)) * 64);
        const uint4* Kg = (const uint4*)(g_Kf + ((size_t)(b * HW)) * 64);
        for (int e = tid; e < 1024; e += 512) {
            int r = e >> 3, c8 = e & 7;
            uint32_t o = SW128(r * 128 + c8 * 16);
            *(uint4*)(smem + OFF_QF + o) = Qg[e];
            *(uint4*)(smem + OFF_K + o)  = Kg[e];
        }
        const __half* Vg = g_Vf + (size_t)b * 64 * HW;
        for (int e = tid; e < 1024; e += 512) {
            int c = e >> 4, j8 = e & 15;
            uint4 val = *(const uint4*)(Vg + (size_t)c * HW + j8 * 8);
            *(uint4*)(smem + OFF_V + (j8 >> 3) * 8192 +
                      SW128(c * 128 + (j8 & 7) * 16)) = val;
        }
        if (tid < 128) *(float*)(smem + OFF_AW + tid * 4) = fabsf(g_w[b * HW + tid]);
    }
    __syncthreads();

    float o[8][4];
    #pragma unroll
    for (int ct = 0; ct < 8; ct++)
        o[ct][0] = o[ct][1] = o[ct][2] = o[ct][3] = 0.f;
    float mrow0 = -1e30f, mrow1 = -1e30f, den0 = 0.f, den1 = 0.f;

    const int qrow = q0w + (lane & 15);

    for (int t = 0; t < 32; t++) {
        const int buf = t & 1;

        if (t < 31) {
            const int m1 = (t + 1) * 128, nb = buf ^ 1;
            const uint4* Kg = (const uint4*)(g_Kf + ((size_t)(b * HW + m1)) * 64);
            char* kb = smem + OFF_K + nb * 16384;
            for (int e = tid; e < 1024; e += 512) {
                int r = e >> 3, c8 = e & 7;
                *(uint4*)(kb + SW128(r * 128 + c8 * 16)) = Kg[e];
            }
            const __half* Vg = g_Vf + (size_t)b * 64 * HW + m1;
            char* vb = smem + OFF_V + nb * 16384;
            for (int e = tid; e < 1024; e += 512) {
                int c = e >> 4, j8 = e & 15;
                uint4 val = *(const uint4*)(Vg + (size_t)c * HW + j8 * 8);
                *(uint4*)(vb + (j8 >> 3) * 8192 +
                          SW128(c * 128 + (j8 & 7) * 16)) = val;
            }
            if (tid < 128)
                *(float*)(smem + OFF_AW + nb * 512 + tid * 4) =
                    fabsf(g_w[b * HW + m1 + tid]);
        }

        const uint32_t k_b  = sbase + OFF_K + buf * 16384;
        const float*   awp  = (const float*)(smem + OFF_AW + buf * 512);

        uint32_t qf[4][4];
        #pragma unroll
        for (int ks = 0; ks < 4; ks++) {
            const uint32_t cb = ks * 32 + (lane >> 4) * 16;
            LDMX4(qf[ks], sbase + OFF_QF + SW128(qrow * 128 + cb));
        }

        float s[8][4];
        #pragma unroll
        for (int i = 0; i < 8; i++)
            s[i][0] = s[i][1] = s[i][2] = s[i][3] = 0.f;

        #pragma unroll
        for (int i = 0; i < 8; i++) {
            const int nt = half * 8 + i;
            const uint32_t roff = (nt * 8 + (lane & 7)) * 128 + (lane >> 3) * 16;
            uint32_t bh[8];
            LDMX4(bh,     k_b + SW128(roff));
            LDMX4(bh + 4, k_b + SW128(roff + 64));
            #pragma unroll
            for (int ks = 0; ks < 4; ks++)
                MMA16816(s[i], qf[ks], bh[2 * ks], bh[2 * ks + 1]);
        }

        float mx0 = s[0][0], mx1 = s[0][2];
        #pragma unroll
        for (int i = 0; i < 8; i++) {
            mx0 = fmaxf(mx0, fmaxf(s[i][0], s[i][1]));
            mx1 = fmaxf(mx1, fmaxf(s[i][2], s[i][3]));
        }
        mx0 = fmaxf(mx0, __shfl_xor_sync(0xffffffffu, mx0, 1));
        mx0 = fmaxf(mx0, __shfl_xor_sync(0xffffffffu, mx0, 2));
        mx1 = fmaxf(mx1, __shfl_xor_sync(0xffffffffu, mx1, 1));
        mx1 = fmaxf(mx1, __shfl_xor_sync(0xffffffffu, mx1, 2));

        const float mn0 = fmaxf(mrow0, mx0), mn1 = fmaxf(mrow1, mx1);
        const float cr0 = ex2f(mrow0 - mn0), cr1 = ex2f(mrow1 - mn1);
        mrow0 = mn0; mrow1 = mn1;

        float ws0 = 0.f, ws1 = 0.f;
        uint32_t aP[4][4];
        #pragma unroll
        for (int i = 0; i < 8; i++) {
            const float2 aw = *(const float2*)&awp[half * 64 + i * 8 + 2 * u];
            uint32_t h01 = ex2_h2(f16x2_pack(s[i][0] - mn0, s[i][1] - mn0));
            uint32_t h23 = ex2_h2(f16x2_pack(s[i][2] - mn1, s[i][3] - mn1));
            aP[i >> 1][(i & 1) * 2]     = h01;
            aP[i >> 1][(i & 1) * 2 + 1] = h23;
            const float2 p01 = __half22float2(*(const __half2*)&h01);
            const float2 p23 = __half22float2(*(const __half2*)&h23);
            ws0 += p01.x * aw.x + p01.y * aw.y;
            ws1 += p23.x * aw.x + p23.y * aw.y;
        }
        ws0 += __shfl_xor_sync(0xffffffffu, ws0, 1);
        ws0 += __shfl_xor_sync(0xffffffffu, ws0, 2);
        ws1 += __shfl_xor_sync(0xffffffffu, ws1, 1);
        ws1 += __shfl_xor_sync(0xffffffffu, ws1, 2);
        den0 = den0 * cr0 + ws0;
        den1 = den1 * cr1 + ws1;

        #pragma unroll
        for (int ct = 0; ct < 8; ct++) {
            o[ct][0] *= cr0; o[ct][1] *= cr0;
            o[ct][2] *= cr1; o[ct][3] *= cr1;
        }

        const uint32_t v_b = sbase + OFF_V + buf * 16384 + half * 8192;
        #pragma unroll
        for (int ct = 0; ct < 8; ct++) {
            const uint32_t roff = (ct * 8 + (lane & 7)) * 128 + (lane >> 3) * 16;
            uint32_t vb[8];
            LDMX4(vb,     v_b + SW128(roff));
            LDMX4(vb + 4, v_b + SW128(roff + 64));
            #pragma unroll
            for (int j = 0; j < 4; j++)
                MMA16816(o[ct], aP[j], vb[2 * j], vb[2 * j + 1]);
        }
        __syncthreads();
    }

    const int r0 = q0w + g, r1 = q0w + g + 8;
    float* msh = (float*)(smem + OFF_MSH);
    float* dsh = (float*)(smem + OFF_DSH);
    if (u == 0) {
        msh[half * 128 + r0] = mrow0;  msh[half * 128 + r1] = mrow1;
        dsh[half * 128 + r0] = den0;   dsh[half * 128 + r1] = den1;
    }
    __syncthreads();

    const float g0 = gamma[0];
    const float mo0 = msh[(1 - half) * 128 + r0], do0 = dsh[(1 - half) * 128 + r0];
    const float mo1 = msh[(1 - half) * 128 + r1], do1 = dsh[(1 - half) * 128 + r1];
    const float mf0 = fmaxf(mrow0, mo0), mf1 = fmaxf(mrow1, mo1);
    const float sm0 = ex2f(mrow0 - mf0), sm1 = ex2f(mrow1 - mf1);
    const float df0 = den0 * sm0 + do0 * ex2f(mo0 - mf0);
    const float df1 = den1 * sm1 + do1 * ex2f(mo1 - mf1);
    const float inv0 = g0 * sm0 / df0, inv1 = g0 * sm1 / df1;

    float* Ost = (float*)(smem + (half ? OFF_OST1 : OFF_OST0));
    #pragma unroll
    for (int ct = 0; ct < 8; ct++) {
        const int c = ct * 8 + 2 * u;
        Ost[c * 128 + r0]       = o[ct][0] * inv0;
        Ost[(c + 1) * 128 + r0] = o[ct][1] * inv0;
        Ost[c * 128 + r1]       = o[ct][2] * inv1;
        Ost[(c + 1) * 128 + r1] = o[ct][3] * inv1;
    }
    __syncthreads();

    const float* O0 = (const float*)(smem + OFF_OST0);
    const float* O1 = (const float*)(smem + OFF_OST1);
    for (int e = tid; e < 2048; e += 512) {
        const int c = e >> 5, q4 = (e & 31) * 4;
        const int idx = c * 128 + q4;
        float4 a = *(const float4*)&O0[idx];
        const float4 bb = *(const float4*)&O1[idx];
        const size_t off = (size_t)(b * 64 + c) * HW + n0 + q4;
        const float4 xv = *(const float4*)&x[off];
        a.x += bb.x + xv.x; a.y += bb.y + xv.y;
        a.z += bb.z + xv.z; a.w += bb.w + xv.w;
        *(float4*)&out[off] = a;
    }
}

// ================= launch =================
extern "C" void kernel_launch(void* const* d_in, const int* in_sizes, int n_in,
                              void* d_out, int out_size)
{
    (void)in_sizes; (void)n_in; (void)out_size;
    const float* x       = (const float*)d_in[0];
    const float* Wq      = (const float*)d_in[1];
    const float* bq      = (const float*)d_in[2];
    const float* Wk      = (const float*)d_in[3];
    const float* bk      = (const float*)d_in[4];
    const float* Wv      = (const float*)d_in[5];
    const float* bv      = (const float*)d_in[6];
    const float* We1     = (const float*)d_in[7];
    const float* be1     = (const float*)d_in[8];
    const float* bn_w    = (const float*)d_in[9];
    const float* bn_b    = (const float*)d_in[10];
    const float* bn_mean = (const float*)d_in[11];
    const float* bn_var  = (const float*)d_in[12];
    const float* We2     = (const float*)d_in[13];
    const float* be2     = (const float*)d_in[14];
    const float* gamma   = (const float*)d_in[15];
    const float* beta    = (const float*)d_in[16];
    float* out = (float*)d_out;

    cudaFuncSetAttribute(edge_kernel, cudaFuncAttributeMaxDynamicSharedMemorySize,
                         EDGE_SMEM);
    edge_kernel<<<dim3(32, NB), 512, EDGE_SMEM>>>(x, We1, be1, bn_w, bn_b,
                                                  bn_mean, bn_var, We2, be2, beta);
    qkv_kernel<<<dim3(32, NB), 384>>>(x, Wq, bq, Wk, bk, Wv, bv);

    cudaFuncSetAttribute(flash_kernel, cudaFuncAttributeMaxDynamicSharedMemorySize,
                         SMEM_BYTES);
    flash_kernel<<<dim3(32, NB), 512, SMEM_BYTES>>>(x, gamma, out);
}

// round 14
// speedup vs baseline: 1.0524x; 1.0524x over previous
#include <cuda_runtime.h>
#include <cuda_fp16.h>
#include <cstdint>

#define HW    4096
#define NB    4
#define LOG2E 1.44269504088896340736f

// ---------------- scratch (device globals: allocation-free) ----------------
__device__ __half g_Qf[NB * HW * 64];   // [b][n][c] fp16, pre-scaled by log2e
__device__ __half g_Kf[NB * HW * 64];   // [b][n][c] fp16
__device__ __half g_Vf[NB * 64 * HW];   // [b][c][m] fp16 (w folded in)
__device__ float  g_w [NB * HW];        // w[m] = 1 + beta*edge

// ---------------- helpers ----------------
__device__ __forceinline__ double dup2(float x) {
    double r; asm("mov.b64 %0, {%1,%1};" : "=d"(r) : "f"(x)); return r;
}
__device__ __forceinline__ void ffma2(double &d, double a, double b) {
    asm("fma.rn.f32x2 %0, %1, %2, %0;" : "+d"(d) : "d"(a), "d"(b));
}
__device__ __forceinline__ void unpack2(double v, float &lo, float &hi) {
    asm("mov.b64 {%0,%1}, %2;" : "=f"(lo), "=f"(hi) : "d"(v));
}
__device__ __forceinline__ float ex2f(float x) {
    float r; asm("ex2.approx.f32 %0, %1;" : "=f"(r) : "f"(x)); return r;
}
__device__ __forceinline__ uint32_t f16x2_pack(float lo, float hi) {
    uint32_t r; asm("cvt.rn.f16x2.f32 %0, %1, %2;" : "=r"(r) : "f"(hi), "f"(lo));
    return r;
}
__device__ __forceinline__ uint32_t ex2_h2(uint32_t h2) {
    asm("ex2.approx.f16x2 %0, %0;" : "+r"(h2));
    return h2;
}
__device__ __forceinline__ uint32_t movm_trans(uint32_t a) {
    uint32_t d;
    asm("movmatrix.sync.aligned.m8n8.trans.b16 %0, %1;" : "=r"(d) : "r"(a));
    return d;
}
__device__ __forceinline__ uint32_t smem_u32(const void* p) {
    uint32_t a;
    asm("{ .reg .u64 t; cvta.to.shared.u64 t, %1; cvt.u32.u64 %0, t; }"
        : "=r"(a) : "l"(p));
    return a;
}

#define SW128(o) ((o) ^ (((o) >> 3) & 0x70))
#define SWX(o)   ((o) ^ (((o) >> 4) & 0x70))

// ---------------- mma.sync / ldmatrix (fp16) ----------------
#define LDMX4(r, addr) \
    asm volatile("ldmatrix.sync.aligned.m8n8.x4.shared.b16 {%0,%1,%2,%3}, [%4];" \
        : "=r"((r)[0]), "=r"((r)[1]), "=r"((r)[2]), "=r"((r)[3]) : "r"(addr))

#define LDMX4T(r, addr) \
    asm volatile("ldmatrix.sync.aligned.m8n8.x4.trans.shared.b16 {%0,%1,%2,%3}, [%4];" \
        : "=r"((r)[0]), "=r"((r)[1]), "=r"((r)[2]), "=r"((r)[3]) : "r"(addr))

#define MMA16816(d, a, b0, b1) \
    asm volatile("mma.sync.aligned.m16n8k16.row.col.f32.f16.f16.f32 " \
        "{%0,%1,%2,%3},{%4,%5,%6,%7},{%8,%9},{%0,%1,%2,%3};" \
        : "+f"((d)[0]), "+f"((d)[1]), "+f"((d)[2]), "+f"((d)[3]) \
        : "r"((a)[0]), "r"((a)[1]), "r"((a)[2]), "r"((a)[3]), "r"(b0), "r"(b1))

// ================= kernel 1: edge detector -> g_w (R13 proven) ============
#define XT_FLOATS (64 * 4 * 66)
#define WS_FLOATS (64 * 9 * 32)
#define RED_STRIDE 34
#define RED_FLOATS (3 * 128 * RED_STRIDE)
#define EDGE_SMEM ((XT_FLOATS + WS_FLOATS + RED_FLOATS) * 4)   // 193536 B

__global__ __launch_bounds__(512) void edge_kernel(
    const float* __restrict__ x,  const float* __restrict__ We1,
    const float* __restrict__ be1,
    const float* __restrict__ bn_w, const float* __restrict__ bn_b,
    const float* __restrict__ bn_mean, const float* __restrict__ bn_var,
    const float* __restrict__ We2, const float* __restrict__ be2,
    const float* __restrict__ beta)
{
    extern __shared__ float es[];
    float* xt  = es;
    float* Wsh = es + XT_FLOATS;
    float* red = es + XT_FLOATS + WS_FLOATS;
    __shared__ float s_sc[32], s_sh[32], s_w2[32];

    const int tid = threadIdx.x;
    const int b   = blockIdx.y;
    const int pr0 = blockIdx.x * 2;

    if (tid < 32) {
        float s = bn_w[tid] * rsqrtf(bn_var[tid] + 1e-5f);
        s_sc[tid] = s;
        s_sh[tid] = (be1[tid] - bn_mean[tid]) * s + bn_b[tid];
        s_w2[tid] = We2[tid];
    }

    for (int e = tid; e < WS_FLOATS; e += 512) {
        int ch = e & 31, rest = e >> 5;
        int k = rest % 9, cc = rest / 9;
        Wsh[e] = We1[(ch * 64 + cc) * 9 + k];
    }
    for (int e = tid; e < XT_FLOATS; e += 512) {
        int c66 = e % 66, rest = e / 66;
        int r = rest & 3, ch = rest >> 2;
        int ir = pr0 - 1 + r, ic = c66 - 1;
        float v = 0.f;
        if (ir >= 0 && ir < 64 && ic >= 0 && ic < 64)
            v = x[(size_t)(b * 64 + ch) * HW + ir * 64 + ic];
        xt[e] = v;
    }
    __syncthreads();

    const int wid  = tid >> 5, lane = tid & 31;
    const int cu   = wid >> 2;
    const int px   = (wid & 3) * 32 + lane;
    const int pr   = px >> 6, col = px & 63;

    double acc2[16];
    #pragma unroll
    for (int i = 0; i < 16; i++) acc2[i] = 0.0;

    for (int ccl = 0; ccl < 16; ccl++) {
        const int cc = cu * 16 + ccl;
        const float* xb = &xt[(cc * 4 + pr) * 66 + col];
        float xv[9];
        #pragma unroll
        for (int ry = 0; ry < 3; ry++)
            #pragma unroll
            for (int rx = 0; rx < 3; rx++)
                xv[ry * 3 + rx] = xb[ry * 66 + rx];
        #pragma unroll
        for (int k = 0; k < 9; k++) {
            double dv = dup2(xv[k]);
            const double2* wrow = (const double2*)&Wsh[(cc * 9 + k) * 32];
            #pragma unroll
            for (int c4 = 0; c4 < 8; c4++) {
                const double2 w2 = wrow[c4];
                ffma2(acc2[2 * c4],     dv, w2.x);
                ffma2(acc2[2 * c4 + 1], dv, w2.y);
            }
        }
    }

    if (cu != 0) {
        double* rp = (double*)&red[((cu - 1) * 128 + px) * RED_STRIDE];
        #pragma unroll
        for (int i = 0; i < 16; i++) rp[i] = acc2[i];
    }
    __syncthreads();
    if (cu == 0) {
        const double* rp1 = (const double*)&red[(px)       * RED_STRIDE];
        const double* rp2 = (const double*)&red[(128 + px) * RED_STRIDE];
        const double* rp3 = (const double*)&red[(256 + px) * RED_STRIDE];
        float e2 = be2[0];
        #pragma unroll
        for (int c2 = 0; c2 < 16; c2++) {
            float a0, a1, p0, p1;
            unpack2(acc2[c2], a0, a1);
            unpack2(rp1[c2], p0, p1); a0 += p0; a1 += p1;
            unpack2(rp2[c2], p0, p1); a0 += p0; a1 += p1;
            unpack2(rp3[c2], p0, p1); a0 += p0; a1 += p1;
            const int ch = c2 * 2;
            float r0 = fmaxf(a0 * s_sc[ch]     + s_sh[ch],     0.f);
            float r1 = fmaxf(a1 * s_sc[ch + 1] + s_sh[ch + 1], 0.f);
            e2 += s_w2[ch] * r0 + s_w2[ch + 1] * r1;
        }
        float sig = 1.f / (1.f + ex2f(-e2 * LOG2E));
        g_w[b * HW + pr0 * 64 + px] = 1.f + beta[0] * sig;
    }
}

// ================= kernel 2: QKV via HMMA (R12 proven) =================
__global__ __launch_bounds__(384) void qkv_kernel(
    const float* __restrict__ x,
    const float* __restrict__ Wq, const float* __restrict__ bq,
    const float* __restrict__ Wk, const float* __restrict__ bk,
    const float* __restrict__ Wv, const float* __restrict__ bv)
{
    __shared__ __align__(16) __half Wf[192 * 64];
    __shared__ __align__(16) __half xB[64 * 128];
    __shared__ float sb[192];
    __shared__ float wvs[128];

    const int tid = threadIdx.x;
    const int b   = blockIdx.y;
    const int n0  = blockIdx.x * 128;
    const uint32_t wf_b = smem_u32(Wf);
    const uint32_t xb_b = smem_u32(xB);

    for (int e = tid; e < 1536; e += 384) {
        int oc = e >> 3, chv = e & 7;
        const float* wsrc;
        float scale = 1.f;
        if (oc < 64)       { wsrc = Wq + oc * 64;        scale = LOG2E; }
        else if (oc < 128) { wsrc = Wk + (oc - 64) * 64; }
        else               { wsrc = Wv + (oc - 128) * 64; }
        const float4 f0 = *(const float4*)(wsrc + chv * 8);
        const float4 f1 = *(const float4*)(wsrc + chv * 8 + 4);
        __half2 h[4];
        h[0] = __floats2half2_rn(f0.x * scale, f0.y * scale);
        h[1] = __floats2half2_rn(f0.z * scale, f0.w * scale);
        h[2] = __floats2half2_rn(f1.x * scale, f1.y * scale);
        h[3] = __floats2half2_rn(f1.z * scale, f1.w * scale);
        *(uint4*)((char*)Wf + SW128(oc * 128 + chv * 16)) = *(uint4*)h;
    }
    for (int e = tid; e < 1024; e += 384) {
        int c = e >> 4, ch = e & 15;
        const float* xp = x + (size_t)(b * 64 + c) * HW + n0 + ch * 8;
        const float4 f0 = *(const float4*)xp;
        const float4 f1 = *(const float4*)(xp + 4);
        __half2 h[4];
        h[0] = __floats2half2_rn(f0.x, f0.y);
        h[1] = __floats2half2_rn(f0.z, f0.w);
        h[2] = __floats2half2_rn(f1.x, f1.y);
        h[3] = __floats2half2_rn(f1.z, f1.w);
        *(uint4*)((char*)xB + SWX(c * 256 + ch * 16)) = *(uint4*)h;
    }
    if (tid < 192)
        sb[tid] = (tid < 64) ? bq[tid] * LOG2E
                 : (tid < 128) ? bk[tid - 64] : bv[tid - 128];
    if (tid < 128) wvs[tid] = g_w[b * HW + n0 + tid];
    __syncthreads();

    const int wid  = tid >> 5, lane = tid & 31;
    const int g    = lane >> 2, u = lane & 3;
    const int mt   = wid;
    const int oc_b = mt * 16;

    uint32_t aW[4][4];
    #pragma unroll
    for (int ks = 0; ks < 4; ks++)
        LDMX4(aW[ks], wf_b + SW128((oc_b + (lane & 15)) * 128 +
                                   ks * 32 + (lane >> 4) * 16));

    float s[16][4];
    #pragma unroll
    for (int i = 0; i < 16; i++)
        s[i][0] = s[i][1] = s[i][2] = s[i][3] = 0.f;

    #pragma unroll
    for (int nt2 = 0; nt2 < 8; nt2++) {
        #pragma unroll
        for (int ks = 0; ks < 4; ks++) {
            uint32_t bb[4];
            LDMX4T(bb, xb_b + SWX((ks * 16 + (lane & 15)) * 256 +
                                  nt2 * 32 + (lane >> 4) * 16));
            MMA16816(s[2 * nt2],     aW[ks], bb[0], bb[1]);
            MMA16816(s[2 * nt2 + 1], aW[ks], bb[2], bb[3]);
        }
    }

    const float b0 = sb[oc_b + g], b1 = sb[oc_b + 8 + g];
    const bool isV = (mt >= 8);
    #pragma unroll
    for (int nt = 0; nt < 16; nt++) {
        const int nn = nt * 8 + 2 * u;
        float v00 = s[nt][0] + b0, v01 = s[nt][1] + b0;
        float v10 = s[nt][2] + b1, v11 = s[nt][3] + b1;
        if (isV) {
            const float w0 = wvs[nn], w1 = wvs[nn + 1];
            v00 *= w0; v01 *= w1; v10 *= w0; v11 *= w1;
        }
        uint32_t h0 = f16x2_pack(v00, v01);
        uint32_t h1 = f16x2_pack(v10, v11);
        if (isV) {
            const size_t vb = (size_t)(b * 64 + (oc_b - 128) + g) * HW + n0 + nn;
            *(uint32_t*)(g_Vf + vb)          = h0;
            *(uint32_t*)(g_Vf + vb + 8 * HW) = h1;
        } else {
            uint32_t t0 = movm_trans(h0);
            uint32_t t1 = movm_trans(h1);
            const int n = nt * 8 + g;
            __half* dst = (mt < 4) ? g_Qf : g_Kf;
            const int cb = (mt < 4) ? oc_b : oc_b - 64;
            const size_t qb = (size_t)(b * HW + n0 + n) * 64 + cb + 2 * u;
            *(uint32_t*)(dst + qb)     = t0;
            *(uint32_t*)(dst + qb + 8) = t1;
        }
    }
}

// ================= kernel 3: fp16 flash, den folded into PV mma ===========
// V smem: per buf, 2 key-halves of [72 c-rows][64 m] (rows 64 = |w|, 65-71 = 0)
#define OFF_QF 0            // 16KB
#define OFF_K  16384        // 2 bufs * 16KB
#define VHALF  9216         // 72 rows * 128B
#define VBUF   (2 * VHALF)  // 18432
#define OFF_V  49152        // 2 bufs * VBUF = 36864
#define SMEM_BYTES 86400
// epilogue overlay:
#define OFF_OST0 0
#define OFF_OST1 32768
#define OFF_MSH  65536
#define OFF_DSH  66560

__global__ __launch_bounds__(512, 1) void flash_kernel(
    const float* __restrict__ x, const float* __restrict__ gamma,
    float* __restrict__ out)
{
    extern __shared__ char smem[];
    const uint32_t sbase = smem_u32(smem);
    const int tid  = threadIdx.x;
    const int lane = tid & 31, wid = tid >> 5;
    const int qg   = wid & 7;
    const int half = wid >> 3;
    const int g    = lane >> 2;
    const int u    = lane & 3;
    const int q0w  = qg * 16;
    const int b    = blockIdx.y;
    const int n0   = blockIdx.x * 128;

    {
        const uint4* Qg = (const uint4*)(g_Qf + ((size_t)(b * HW + n0)) * 64);
        const uint4* Kg = (const uint4*)(g_Kf + ((size_t)(b * HW)) * 64);
        for (int e = tid; e < 1024; e += 512) {
            int r = e >> 3, c8 = e & 7;
            uint32_t o = SW128(r * 128 + c8 * 16);
            *(uint4*)(smem + OFF_QF + o) = Qg[e];
            *(uint4*)(smem + OFF_K + o)  = Kg[e];
        }
        const __half* Vg = g_Vf + (size_t)b * 64 * HW;
        for (int e = tid; e < 1024; e += 512) {
            int c = e >> 4, j8 = e & 15;
            uint4 val = *(const uint4*)(Vg + (size_t)c * HW + j8 * 8);
            *(uint4*)(smem + OFF_V + (j8 >> 3) * VHALF +
                      SW128(c * 128 + (j8 & 7) * 16)) = val;
        }
        // zero rows 65-71 of every V block (both bufs, both halves) — constant
        const uint4 zz = make_uint4(0, 0, 0, 0);
        for (int e = tid; e < 224; e += 512) {
            int buf = e / 112, rest = e % 112;
            int h = rest / 56, r = rest % 56;
            int row = 65 + r / 8, c16 = r % 8;
            *(uint4*)(smem + OFF_V + buf * VBUF + h * VHALF +
                      SW128(row * 128 + c16 * 16)) = zz;
        }
        // |w| row (row 64) for tile 0
        if (tid < 16) {
            int h = tid >> 3, grp = tid & 7;
            const float* wp = g_w + b * HW + h * 64 + grp * 8;
            __half hv[8];
            #pragma unroll
            for (int i = 0; i < 8; i++) hv[i] = __float2half(fabsf(wp[i]));
            *(uint4*)(smem + OFF_V + h * VHALF + SW128(64 * 128 + grp * 16)) =
                *(uint4*)hv;
        }
    }
    __syncthreads();

    float o[9][4];                      // [0..7]=channels, [8]=den column
    #pragma unroll
    for (int ct = 0; ct < 9; ct++)
        o[ct][0] = o[ct][1] = o[ct][2] = o[ct][3] = 0.f;
    float mrow0 = -1e30f, mrow1 = -1e30f;

    const int qrow = q0w + (lane & 15);

    for (int t = 0; t < 32; t++) {
        const int buf = t & 1;

        if (t < 31) {
            const int m1 = (t + 1) * 128, nb = buf ^ 1;
            const uint4* Kg = (const uint4*)(g_Kf + ((size_t)(b * HW + m1)) * 64);
            char* kb = smem + OFF_K + nb * 16384;
            for (int e = tid; e < 1024; e += 512) {
                int r = e >> 3, c8 = e & 7;
                *(uint4*)(kb + SW128(r * 128 + c8 * 16)) = Kg[e];
            }
            const __half* Vg = g_Vf + (size_t)b * 64 * HW + m1;
            char* vb = smem + OFF_V + nb * VBUF;
            for (int e = tid; e < 1024; e += 512) {
                int c = e >> 4, j8 = e & 15;
                uint4 val = *(const uint4*)(Vg + (size_t)c * HW + j8 * 8);
                *(uint4*)(vb + (j8 >> 3) * VHALF +
                          SW128(c * 128 + (j8 & 7) * 16)) = val;
            }
            if (tid < 16) {
                int h = tid >> 3, grp = tid & 7;
                const float* wp = g_w + b * HW + m1 + h * 64 + grp * 8;
                __half hv[8];
                #pragma unroll
                for (int i = 0; i < 8; i++) hv[i] = __float2half(fabsf(wp[i]));
                *(uint4*)(vb + h * VHALF + SW128(64 * 128 + grp * 16)) =
                    *(uint4*)hv;
            }
        }

        const uint32_t k_b = sbase + OFF_K + buf * 16384;

        // ---- reload Q fragments (short live range) ----
        uint32_t qf[4][4];
        #pragma unroll
        for (int ks = 0; ks < 4; ks++) {
            const uint32_t cb = ks * 32 + (lane >> 4) * 16;
            LDMX4(qf[ks], sbase + OFF_QF + SW128(qrow * 128 + cb));
        }

        // ---- S = QK^T for this warp's 64 keys ----
        float s[8][4];
        #pragma unroll
        for (int i = 0; i < 8; i++)
            s[i][0] = s[i][1] = s[i][2] = s[i][3] = 0.f;

        #pragma unroll
        for (int i = 0; i < 8; i++) {
            const int nt = half * 8 + i;
            const uint32_t roff = (nt * 8 + (lane & 7)) * 128 + (lane >> 3) * 16;
            uint32_t bh[8];
            LDMX4(bh,     k_b + SW128(roff));
            LDMX4(bh + 4, k_b + SW128(roff + 64));
            #pragma unroll
            for (int ks = 0; ks < 4; ks++)
                MMA16816(s[i], qf[ks], bh[2 * ks], bh[2 * ks + 1]);
        }

        // ---- online max (quad-local) ----
        float mx0 = s[0][0], mx1 = s[0][2];
        #pragma unroll
        for (int i = 0; i < 8; i++) {
            mx0 = fmaxf(mx0, fmaxf(s[i][0], s[i][1]));
            mx1 = fmaxf(mx1, fmaxf(s[i][2], s[i][3]));
        }
        mx0 = fmaxf(mx0, __shfl_xor_sync(0xffffffffu, mx0, 1));
        mx0 = fmaxf(mx0, __shfl_xor_sync(0xffffffffu, mx0, 2));
        mx1 = fmaxf(mx1, __shfl_xor_sync(0xffffffffu, mx1, 1));
        mx1 = fmaxf(mx1, __shfl_xor_sync(0xffffffffu, mx1, 2));

        const float mn0 = fmaxf(mrow0, mx0), mn1 = fmaxf(mrow1, mx1);
        const float cr0 = ex2f(mrow0 - mn0), cr1 = ex2f(mrow1 - mn1);
        mrow0 = mn0; mrow1 = mn1;

        // ---- p = exp2(s - mn) directly as fp16x2 A-fragments ----
        uint32_t aP[4][4];
        #pragma unroll
        for (int i = 0; i < 8; i++) {
            aP[i >> 1][(i & 1) * 2] =
                ex2_h2(f16x2_pack(s[i][0] - mn0, s[i][1] - mn0));
            aP[i >> 1][(i & 1) * 2 + 1] =
                ex2_h2(f16x2_pack(s[i][2] - mn1, s[i][3] - mn1));
        }

        // ---- rescale accumulators (incl. den column) ----
        #pragma unroll
        for (int ct = 0; ct < 9; ct++) {
            o[ct][0] *= cr0; o[ct][1] *= cr0;
            o[ct][2] *= cr1; o[ct][3] *= cr1;
        }

        // ---- O += P * [Vw | |w|]  (9 n-tiles; tile 8 accumulates den) ----
        const uint32_t v_b = sbase + OFF_V + buf * VBUF + half * VHALF;
        #pragma unroll
        for (int ct = 0; ct < 9; ct++) {
            const uint32_t roff = (ct * 8 + (lane & 7)) * 128 + (lane >> 3) * 16;
            uint32_t vb[8];
            LDMX4(vb,     v_b + SW128(roff));
            LDMX4(vb + 4, v_b + SW128(roff + 64));
            #pragma unroll
            for (int j = 0; j < 4; j++)
                MMA16816(o[ct], aP[j], vb[2 * j], vb[2 * j + 1]);
        }
        __syncthreads();
    }

    // ---- den lives in o[8] col 64 (u==0 lane of each quad) ----
    const float den0 = __shfl_sync(0xffffffffu, o[8][0], lane & 28);
    const float den1 = __shfl_sync(0xffffffffu, o[8][2], lane & 28);

    // ---- merge the two key-half chains, stage, write ----
    const int r0 = q0w + g, r1 = q0w + g + 8;
    float* msh = (float*)(smem + OFF_MSH);
    float* dsh = (float*)(smem + OFF_DSH);
    if (u == 0) {
        msh[half * 128 + r0] = mrow0;  msh[half * 128 + r1] = mrow1;
        dsh[half * 128 + r0] = den0;   dsh[half * 128 + r1] = den1;
    }
    __syncthreads();

    const float g0 = gamma[0];
    const float mo0 = msh[(1 - half) * 128 + r0], do0 = dsh[(1 - half) * 128 + r0];
    const float mo1 = msh[(1 - half) * 128 + r1], do1 = dsh[(1 - half) * 128 + r1];
    const float mf0 = fmaxf(mrow0, mo0), mf1 = fmaxf(mrow1, mo1);
    const float sm0 = ex2f(mrow0 - mf0), sm1 = ex2f(mrow1 - mf1);
    const float df0 = den0 * sm0 + do0 * ex2f(mo0 - mf0);
    const float df1 = den1 * sm1 + do1 * ex2f(mo1 - mf1);
    const float inv0 = g0 * sm0 / df0, inv1 = g0 * sm1 / df1;

    float* Ost = (float*)(smem + (half ? OFF_OST1 : OFF_OST0));
    #pragma unroll
    for (int ct = 0; ct < 8; ct++) {
        const int c = ct * 8 + 2 * u;
        Ost[c * 128 + r0]       = o[ct][0] * inv0;
        Ost[(c + 1) * 128 + r0] = o[ct][1] * inv0;
        Ost[c * 128 + r1]       = o[ct][2] * inv1;
        Ost[(c + 1) * 128 + r1] = o[ct][3] * inv1;
    }
    __syncthreads();

    const float* O0 = (const float*)(smem + OFF_OST0);
    const float* O1 = (const float*)(smem + OFF_OST1);
    for (int e = tid; e < 2048; e += 512) {
        const int c = e >> 5, q4 = (e & 31) * 4;
        const int idx = c * 128 + q4;
        float4 a = *(const float4*)&O0[idx];
        const float4 bb = *(const float4*)&O1[idx];
        const size_t off = (size_t)(b * 64 + c) * HW + n0 + q4;
        const float4 xv = *(const float4*)&x[off];
        a.x += bb.x + xv.x; a.y += bb.y + xv.y;
        a.z += bb.z + xv.z; a.w += bb.w + xv.w;
        *(float4*)&out[off] = a;
    }
}

// ================= launch =================
extern "C" void kernel_launch(void* const* d_in, const int* in_sizes, int n_in,
                              void* d_out, int out_size)
{
    (void)in_sizes; (void)n_in; (void)out_size;
    const float* x       = (const float*)d_in[0];
    const float* Wq      = (const float*)d_in[1];
    const float* bq      = (const float*)d_in[2];
    const float* Wk      = (const float*)d_in[3];
    const float* bk      = (const float*)d_in[4];
    const float* Wv      = (const float*)d_in[5];
    const float* bv      = (const float*)d_in[6];
    const float* We1     = (const float*)d_in[7];
    const float* be1     = (const float*)d_in[8];
    const float* bn_w    = (const float*)d_in[9];
    const float* bn_b    = (const float*)d_in[10];
    const float* bn_mean = (const float*)d_in[11];
    const float* bn_var  = (const float*)d_in[12];
    const float* We2     = (const float*)d_in[13];
    const float* be2     = (const float*)d_in[14];
    const float* gamma   = (const float*)d_in[15];
    const float* beta    = (const float*)d_in[16];
    float* out = (float*)d_out;

    cudaFuncSetAttribute(edge_kernel, cudaFuncAttributeMaxDynamicSharedMemorySize,
                         EDGE_SMEM);
    edge_kernel<<<dim3(32, NB), 512, EDGE_SMEM>>>(x, We1, be1, bn_w, bn_b,
                                                  bn_mean, bn_var, We2, be2, beta);
    qkv_kernel<<<dim3(32, NB), 384>>>(x, Wq, bq, Wk, bk, Wv, bv);

    cudaFuncSetAttribute(flash_kernel, cudaFuncAttributeMaxDynamicSharedMemorySize,
                         SMEM_BYTES);
    flash_kernel<<<dim3(32, NB), 512, SMEM_BYTES>>>(x, gamma, out);
}

// round 15
// speedup vs baseline: 1.2656x; 1.2026x over previous
#include <cuda_runtime.h>
#include <cuda_fp16.h>
#include <cstdint>

#define HW    4096
#define NB    4
#define LOG2E 1.44269504088896340736f

// ---------------- scratch (device globals: allocation-free) ----------------
__device__ __half g_Qf[NB * HW * 64];   // [b][n][c] fp16, pre-scaled by log2e
__device__ __half g_Kf[NB * HW * 64];   // [b][n][c] fp16
__device__ __half g_Vf[NB * 64 * HW];   // [b][c][m] fp16 (w folded in)
__device__ float  g_w [NB * HW];        // w[m] = 1 + beta*edge

// ---------------- helpers ----------------
__device__ __forceinline__ float ex2f(float x) {
    float r; asm("ex2.approx.f32 %0, %1;" : "=f"(r) : "f"(x)); return r;
}
__device__ __forceinline__ uint32_t f16x2_pack(float lo, float hi) {
    uint32_t r; asm("cvt.rn.f16x2.f32 %0, %1, %2;" : "=r"(r) : "f"(hi), "f"(lo));
    return r;
}
__device__ __forceinline__ uint32_t ex2_h2(uint32_t h2) {
    asm("ex2.approx.f16x2 %0, %0;" : "+r"(h2));
    return h2;
}
__device__ __forceinline__ uint32_t movm_trans(uint32_t a) {
    uint32_t d;
    asm("movmatrix.sync.aligned.m8n8.trans.b16 %0, %1;" : "=r"(d) : "r"(a));
    return d;
}
__device__ __forceinline__ uint32_t smem_u32(const void* p) {
    uint32_t a;
    asm("{ .reg .u64 t; cvta.to.shared.u64 t, %1; cvt.u32.u64 %0, t; }"
        : "=r"(a) : "l"(p));
    return a;
}

#define SW128(o) ((o) ^ (((o) >> 3) & 0x70))
#define SWX(o)   ((o) ^ (((o) >> 4) & 0x70))

// ---------------- mma.sync / ldmatrix (fp16) ----------------
#define LDMX4(r, addr) \
    asm volatile("ldmatrix.sync.aligned.m8n8.x4.shared.b16 {%0,%1,%2,%3}, [%4];" \
        : "=r"((r)[0]), "=r"((r)[1]), "=r"((r)[2]), "=r"((r)[3]) : "r"(addr))

#define LDMX4T(r, addr) \
    asm volatile("ldmatrix.sync.aligned.m8n8.x4.trans.shared.b16 {%0,%1,%2,%3}, [%4];" \
        : "=r"((r)[0]), "=r"((r)[1]), "=r"((r)[2]), "=r"((r)[3]) : "r"(addr))

#define MMA16816(d, a, b0, b1) \
    asm volatile("mma.sync.aligned.m16n8k16.row.col.f32.f16.f16.f32 " \
        "{%0,%1,%2,%3},{%4,%5,%6,%7},{%8,%9},{%0,%1,%2,%3};" \
        : "+f"((d)[0]), "+f"((d)[1]), "+f"((d)[2]), "+f"((d)[3]) \
        : "r"((a)[0]), "r"((a)[1]), "r"((a)[2]), "r"((a)[3]), "r"(b0), "r"(b1))

// ================= kernel 1: edge detector via HMMA =================
// 3x3 conv as 9 shifted GEMMs. X halo tile token-major [264 pos][64 ch] fp16;
// tap (dy,dx) only shifts the ldmatrix ROW index -> alignment always holds.
// 16 warps = 2 oc-halves x 8 token-16 groups. CTA = 2 image rows (128 px).
#define EW_BYTES (9 * 32 * 128)          // 36864 (tap-major A, SW128)
#define EX_BYTES (264 * 128)             // 33792 (pos-major X, SW128)
#define E_RED    (EW_BYTES + EX_BYTES)   // 70656
#define EDGE_SMEM (E_RED + 128 * 4)      // 71168 B

__global__ __launch_bounds__(512) void edge_kernel(
    const float* __restrict__ x,  const float* __restrict__ We1,
    const float* __restrict__ be1,
    const float* __restrict__ bn_w, const float* __restrict__ bn_b,
    const float* __restrict__ bn_mean, const float* __restrict__ bn_var,
    const float* __restrict__ We2, const float* __restrict__ be2,
    const float* __restrict__ beta)
{
    extern __shared__ char esm[];
    const uint32_t w_b = smem_u32(esm);
    const uint32_t x_b = w_b + EW_BYTES;
    float* red = (float*)(esm + E_RED);
    __shared__ float s_sc[32], s_sh[32], s_w2[32];

    const int tid = threadIdx.x;
    const int b   = blockIdx.y;
    const int pr0 = blockIdx.x * 2;          // image row base

    if (tid < 32) {
        float s = bn_w[tid] * rsqrtf(bn_var[tid] + 1e-5f);
        s_sc[tid] = s;
        s_sh[tid] = (be1[tid] - bn_mean[tid]) * s + bn_b[tid];
        s_w2[tid] = We2[tid];
    }

    // ---- A fill: Wsh[tap][oc 32][ch 64] fp16, SW128 per tap block ----
    for (int e = tid; e < 18432; e += 512) {
        const int oc = e / 576, rest = e % 576;
        const int ci = rest / 9, k = rest % 9;
        *(__half*)(esm + k * 4096 + SW128(oc * 128 + ci * 2)) =
            __float2half(We1[e]);
    }
    // ---- X fill: [pos = (r+1)*66 + (c+1)][64 ch] fp16, zero halo ----
    for (int e = tid; e < 2112; e += 512) {
        const int pos = e >> 3, grp = e & 7;
        const int rr = pos / 66, cc = pos % 66;
        const int ir = pr0 - 1 + rr, ic = cc - 1;
        __half hv[8];
        if (ir >= 0 && ir < 64 && ic >= 0 && ic < 64) {
            const float* xp = x + (size_t)(b * 64 + grp * 8) * HW + ir * 64 + ic;
            #pragma unroll
            for (int i = 0; i < 8; i++) hv[i] = __float2half(xp[(size_t)i * HW]);
        } else {
            #pragma unroll
            for (int i = 0; i < 8; i++) hv[i] = __half(0.f);
        }
        *(uint4*)(esm + EW_BYTES + SW128(pos * 128 + grp * 16)) = *(uint4*)hv;
    }
    __syncthreads();

    const int wid = tid >> 5, lane = tid & 31;
    const int g   = lane >> 2, u = lane & 3;
    const int m   = wid >> 3;                // oc half (0/1)
    const int t8  = wid & 7;                 // token-16 group
    const int oc_b = m * 16;
    const int tr  = t8 >> 2;                 // image row within CTA
    const int tcb = (t8 & 3) * 16;           // col base of the 16 tokens

    float s[2][4];
    s[0][0]=s[0][1]=s[0][2]=s[0][3]=0.f;
    s[1][0]=s[1][1]=s[1][2]=s[1][3]=0.f;

    #pragma unroll
    for (int tap = 0; tap < 9; tap++) {
        const int dy = tap / 3 - 1, dx = tap % 3 - 1;
        uint32_t aW[4][4];
        #pragma unroll
        for (int ks = 0; ks < 4; ks++)
            LDMX4(aW[ks], w_b + tap * 4096 +
                  SW128((oc_b + (lane & 15)) * 128 + ks * 32 + (lane >> 4) * 16));
        const int pbase = (tr + 1 + dy) * 66 + tcb + 1 + dx;
        #pragma unroll
        for (int nt = 0; nt < 2; nt++) {
            uint32_t bh[8];
            const uint32_t ro = (pbase + nt * 8 + (lane & 7)) * 128 +
                                (lane >> 3) * 16;
            LDMX4(bh,     x_b + SW128(ro));
            LDMX4(bh + 4, x_b + SW128(ro + 64));
            #pragma unroll
            for (int ks = 0; ks < 4; ks++)
                MMA16816(s[nt], aW[ks], bh[2 * ks], bh[2 * ks + 1]);
        }
    }

    // ---- epilogue: BN + ReLU + 1x1 partial (16 oc), g-lane reduction ----
    const float sc0 = s_sc[oc_b + g],     sh0 = s_sh[oc_b + g];
    const float sc1 = s_sc[oc_b + 8 + g], sh1 = s_sh[oc_b + 8 + g];
    const float w20 = s_w2[oc_b + g],     w21 = s_w2[oc_b + 8 + g];
    float part[2][2];
    #pragma unroll
    for (int nt = 0; nt < 2; nt++) {
        const float r00 = fmaxf(s[nt][0] * sc0 + sh0, 0.f);
        const float r01 = fmaxf(s[nt][1] * sc0 + sh0, 0.f);
        const float r10 = fmaxf(s[nt][2] * sc1 + sh1, 0.f);
        const float r11 = fmaxf(s[nt][3] * sc1 + sh1, 0.f);
        part[nt][0] = w20 * r00 + w21 * r10;
        part[nt][1] = w20 * r01 + w21 * r11;
        #pragma unroll
        for (int off = 16; off >= 4; off >>= 1) {
            part[nt][0] += __shfl_xor_sync(0xffffffffu, part[nt][0], off);
            part[nt][1] += __shfl_xor_sync(0xffffffffu, part[nt][1], off);
        }
    }

    if (m == 1 && g == 0) {
        #pragma unroll
        for (int nt = 0; nt < 2; nt++) {
            red[t8 * 16 + nt * 8 + 2 * u]     = part[nt][0];
            red[t8 * 16 + nt * 8 + 2 * u + 1] = part[nt][1];
        }
    }
    __syncthreads();
    if (m == 0 && g == 0) {
        const float bb2 = be2[0], bt = beta[0];
        #pragma unroll
        for (int nt = 0; nt < 2; nt++) {
            #pragma unroll
            for (int c = 0; c < 2; c++) {
                const int tok = t8 * 16 + nt * 8 + 2 * u + c;
                const float e2 = bb2 + part[nt][c] + red[tok];
                const float sig = 1.f / (1.f + ex2f(-e2 * LOG2E));
                g_w[b * HW + pr0 * 64 + tok] = 1.f + bt * sig;
            }
        }
    }
}

// ================= kernel 2: QKV via HMMA (R12 proven) =================
__global__ __launch_bounds__(384) void qkv_kernel(
    const float* __restrict__ x,
    const float* __restrict__ Wq, const float* __restrict__ bq,
    const float* __restrict__ Wk, const float* __restrict__ bk,
    const float* __restrict__ Wv, const float* __restrict__ bv)
{
    __shared__ __align__(16) __half Wf[192 * 64];
    __shared__ __align__(16) __half xB[64 * 128];
    __shared__ float sb[192];
    __shared__ float wvs[128];

    const int tid = threadIdx.x;
    const int b   = blockIdx.y;
    const int n0  = blockIdx.x * 128;
    const uint32_t wf_b = smem_u32(Wf);
    const uint32_t xb_b = smem_u32(xB);

    for (int e = tid; e < 1536; e += 384) {
        int oc = e >> 3, chv = e & 7;
        const float* wsrc;
        float scale = 1.f;
        if (oc < 64)       { wsrc = Wq + oc * 64;        scale = LOG2E; }
        else if (oc < 128) { wsrc = Wk + (oc - 64) * 64; }
        else               { wsrc = Wv + (oc - 128) * 64; }
        const float4 f0 = *(const float4*)(wsrc + chv * 8);
        const float4 f1 = *(const float4*)(wsrc + chv * 8 + 4);
        __half2 h[4];
        h[0] = __floats2half2_rn(f0.x * scale, f0.y * scale);
        h[1] = __floats2half2_rn(f0.z * scale, f0.w * scale);
        h[2] = __floats2half2_rn(f1.x * scale, f1.y * scale);
        h[3] = __floats2half2_rn(f1.z * scale, f1.w * scale);
        *(uint4*)((char*)Wf + SW128(oc * 128 + chv * 16)) = *(uint4*)h;
    }
    for (int e = tid; e < 1024; e += 384) {
        int c = e >> 4, ch = e & 15;
        const float* xp = x + (size_t)(b * 64 + c) * HW + n0 + ch * 8;
        const float4 f0 = *(const float4*)xp;
        const float4 f1 = *(const float4*)(xp + 4);
        __half2 h[4];
        h[0] = __floats2half2_rn(f0.x, f0.y);
        h[1] = __floats2half2_rn(f0.z, f0.w);
        h[2] = __floats2half2_rn(f1.x, f1.y);
        h[3] = __floats2half2_rn(f1.z, f1.w);
        *(uint4*)((char*)xB + SWX(c * 256 + ch * 16)) = *(uint4*)h;
    }
    if (tid < 192)
        sb[tid] = (tid < 64) ? bq[tid] * LOG2E
                 : (tid < 128) ? bk[tid - 64] : bv[tid - 128];
    if (tid < 128) wvs[tid] = g_w[b * HW + n0 + tid];
    __syncthreads();

    const int wid  = tid >> 5, lane = tid & 31;
    const int g    = lane >> 2, u = lane & 3;
    const int mt   = wid;
    const int oc_b = mt * 16;

    uint32_t aW[4][4];
    #pragma unroll
    for (int ks = 0; ks < 4; ks++)
        LDMX4(aW[ks], wf_b + SW128((oc_b + (lane & 15)) * 128 +
                                   ks * 32 + (lane >> 4) * 16));

    float s[16][4];
    #pragma unroll
    for (int i = 0; i < 16; i++)
        s[i][0] = s[i][1] = s[i][2] = s[i][3] = 0.f;

    #pragma unroll
    for (int nt2 = 0; nt2 < 8; nt2++) {
        #pragma unroll
        for (int ks = 0; ks < 4; ks++) {
            uint32_t bb[4];
            LDMX4T(bb, xb_b + SWX((ks * 16 + (lane & 15)) * 256 +
                                  nt2 * 32 + (lane >> 4) * 16));
            MMA16816(s[2 * nt2],     aW[ks], bb[0], bb[1]);
            MMA16816(s[2 * nt2 + 1], aW[ks], bb[2], bb[3]);
        }
    }

    const float b0 = sb[oc_b + g], b1 = sb[oc_b + 8 + g];
    const bool isV = (mt >= 8);
    #pragma unroll
    for (int nt = 0; nt < 16; nt++) {
        const int nn = nt * 8 + 2 * u;
        float v00 = s[nt][0] + b0, v01 = s[nt][1] + b0;
        float v10 = s[nt][2] + b1, v11 = s[nt][3] + b1;
        if (isV) {
            const float w0 = wvs[nn], w1 = wvs[nn + 1];
            v00 *= w0; v01 *= w1; v10 *= w0; v11 *= w1;
        }
        uint32_t h0 = f16x2_pack(v00, v01);
        uint32_t h1 = f16x2_pack(v10, v11);
        if (isV) {
            const size_t vb = (size_t)(b * 64 + (oc_b - 128) + g) * HW + n0 + nn;
            *(uint32_t*)(g_Vf + vb)          = h0;
            *(uint32_t*)(g_Vf + vb + 8 * HW) = h1;
        } else {
            uint32_t t0 = movm_trans(h0);
            uint32_t t1 = movm_trans(h1);
            const int n = nt * 8 + g;
            __half* dst = (mt < 4) ? g_Qf : g_Kf;
            const int cb = (mt < 4) ? oc_b : oc_b - 64;
            const size_t qb = (size_t)(b * HW + n0 + n) * 64 + cb + 2 * u;
            *(uint32_t*)(dst + qb)     = t0;
            *(uint32_t*)(dst + qb + 8) = t1;
        }
    }
}

// ================= kernel 3: fp16 flash, den folded into PV mma (R14) =====
#define OFF_QF 0            // 16KB
#define OFF_K  16384        // 2 bufs * 16KB
#define VHALF  9216         // 72 rows * 128B
#define VBUF   (2 * VHALF)
#define OFF_V  49152        // 2 bufs * VBUF
#define SMEM_BYTES 86400
#define OFF_OST0 0
#define OFF_OST1 32768
#define OFF_MSH  65536
#define OFF_DSH  66560

__global__ __launch_bounds__(512, 1) void flash_kernel(
    const float* __restrict__ x, const float* __restrict__ gamma,
    float* __restrict__ out)
{
    extern __shared__ char smem[];
    const uint32_t sbase = smem_u32(smem);
    const int tid  = threadIdx.x;
    const int lane = tid & 31, wid = tid >> 5;
    const int qg   = wid & 7;
    const int half = wid >> 3;
    const int g    = lane >> 2;
    const int u    = lane & 3;
    const int q0w  = qg * 16;
    const int b    = blockIdx.y;
    const int n0   = blockIdx.x * 128;

    {
        const uint4* Qg = (const uint4*)(g_Qf + ((size_t)(b * HW + n0)) * 64);
        const uint4* Kg = (const uint4*)(g_Kf + ((size_t)(b * HW)) * 64);
        for (int e = tid; e < 1024; e += 512) {
            int r = e >> 3, c8 = e & 7;
            uint32_t o = SW128(r * 128 + c8 * 16);
            *(uint4*)(smem + OFF_QF + o) = Qg[e];
            *(uint4*)(smem + OFF_K + o)  = Kg[e];
        }
        const __half* Vg = g_Vf + (size_t)b * 64 * HW;
        for (int e = tid; e < 1024; e += 512) {
            int c = e >> 4, j8 = e & 15;
            uint4 val = *(const uint4*)(Vg + (size_t)c * HW + j8 * 8);
            *(uint4*)(smem + OFF_V + (j8 >> 3) * VHALF +
                      SW128(c * 128 + (j8 & 7) * 16)) = val;
        }
        const uint4 zz = make_uint4(0, 0, 0, 0);
        for (int e = tid; e < 224; e += 512) {
            int buf = e / 112, rest = e % 112;
            int h = rest / 56, r = rest % 56;
            int row = 65 + r / 8, c16 = r % 8;
            *(uint4*)(smem + OFF_V + buf * VBUF + h * VHALF +
                      SW128(row * 128 + c16 * 16)) = zz;
        }
        if (tid < 16) {
            int h = tid >> 3, grp = tid & 7;
            const float* wp = g_w + b * HW + h * 64 + grp * 8;
            __half hv[8];
            #pragma unroll
            for (int i = 0; i < 8; i++) hv[i] = __float2half(fabsf(wp[i]));
            *(uint4*)(smem + OFF_V + h * VHALF + SW128(64 * 128 + grp * 16)) =
                *(uint4*)hv;
        }
    }
    __syncthreads();

    float o[9][4];
    #pragma unroll
    for (int ct = 0; ct < 9; ct++)
        o[ct][0] = o[ct][1] = o[ct][2] = o[ct][3] = 0.f;
    float mrow0 = -1e30f, mrow1 = -1e30f;

    const int qrow = q0w + (lane & 15);

    for (int t = 0; t < 32; t++) {
        const int buf = t & 1;

        if (t < 31) {
            const int m1 = (t + 1) * 128, nb = buf ^ 1;
            const uint4* Kg = (const uint4*)(g_Kf + ((size_t)(b * HW + m1)) * 64);
            char* kb = smem + OFF_K + nb * 16384;
            for (int e = tid; e < 1024; e += 512) {
                int r = e >> 3, c8 = e & 7;
                *(uint4*)(kb + SW128(r * 128 + c8 * 16)) = Kg[e];
            }
            const __half* Vg = g_Vf + (size_t)b * 64 * HW + m1;
            char* vb = smem + OFF_V + nb * VBUF;
            for (int e = tid; e < 1024; e += 512) {
                int c = e >> 4, j8 = e & 15;
                uint4 val = *(const uint4*)(Vg + (size_t)c * HW + j8 * 8);
                *(uint4*)(vb + (j8 >> 3) * VHALF +
                          SW128(c * 128 + (j8 & 7) * 16)) = val;
            }
            if (tid < 16) {
                int h = tid >> 3, grp = tid & 7;
                const float* wp = g_w + b * HW + m1 + h * 64 + grp * 8;
                __half hv[8];
                #pragma unroll
                for (int i = 0; i < 8; i++) hv[i] = __float2half(fabsf(wp[i]));
                *(uint4*)(vb + h * VHALF + SW128(64 * 128 + grp * 16)) =
                    *(uint4*)hv;
            }
        }

        const uint32_t k_b = sbase + OFF_K + buf * 16384;

        uint32_t qf[4][4];
        #pragma unroll
        for (int ks = 0; ks < 4; ks++) {
            const uint32_t cb = ks * 32 + (lane >> 4) * 16;
            LDMX4(qf[ks], sbase + OFF_QF + SW128(qrow * 128 + cb));
        }

        float s[8][4];
        #pragma unroll
        for (int i = 0; i < 8; i++)
            s[i][0] = s[i][1] = s[i][2] = s[i][3] = 0.f;

        #pragma unroll
        for (int i = 0; i < 8; i++) {
            const int nt = half * 8 + i;
            const uint32_t roff = (nt * 8 + (lane & 7)) * 128 + (lane >> 3) * 16;
            uint32_t bh[8];
            LDMX4(bh,     k_b + SW128(roff));
            LDMX4(bh + 4, k_b + SW128(roff + 64));
            #pragma unroll
            for (int ks = 0; ks < 4; ks++)
                MMA16816(s[i], qf[ks], bh[2 * ks], bh[2 * ks + 1]);
        }

        float mx0 = s[0][0], mx1 = s[0][2];
        #pragma unroll
        for (int i = 0; i < 8; i++) {
            mx0 = fmaxf(mx0, fmaxf(s[i][0], s[i][1]));
            mx1 = fmaxf(mx1, fmaxf(s[i][2], s[i][3]));
        }
        mx0 = fmaxf(mx0, __shfl_xor_sync(0xffffffffu, mx0, 1));
        mx0 = fmaxf(mx0, __shfl_xor_sync(0xffffffffu, mx0, 2));
        mx1 = fmaxf(mx1, __shfl_xor_sync(0xffffffffu, mx1, 1));
        mx1 = fmaxf(mx1, __shfl_xor_sync(0xffffffffu, mx1, 2));

        const float mn0 = fmaxf(mrow0, mx0), mn1 = fmaxf(mrow1, mx1);
        const float cr0 = ex2f(mrow0 - mn0), cr1 = ex2f(mrow1 - mn1);
        mrow0 = mn0; mrow1 = mn1;

        uint32_t aP[4][4];
        #pragma unroll
        for (int i = 0; i < 8; i++) {
            aP[i >> 1][(i & 1) * 2] =
                ex2_h2(f16x2_pack(s[i][0] - mn0, s[i][1] - mn0));
            aP[i >> 1][(i & 1) * 2 + 1] =
                ex2_h2(f16x2_pack(s[i][2] - mn1, s[i][3] - mn1));
        }

        #pragma unroll
        for (int ct = 0; ct < 9; ct++) {
            o[ct][0] *= cr0; o[ct][1] *= cr0;
            o[ct][2] *= cr1; o[ct][3] *= cr1;
        }

        const uint32_t v_b = sbase + OFF_V + buf * VBUF + half * VHALF;
        #pragma unroll
        for (int ct = 0; ct < 9; ct++) {
            const uint32_t roff = (ct * 8 + (lane & 7)) * 128 + (lane >> 3) * 16;
            uint32_t vb[8];
            LDMX4(vb,     v_b + SW128(roff));
            LDMX4(vb + 4, v_b + SW128(roff + 64));
            #pragma unroll
            for (int j = 0; j < 4; j++)
                MMA16816(o[ct], aP[j], vb[2 * j], vb[2 * j + 1]);
        }
        __syncthreads();
    }

    const float den0 = __shfl_sync(0xffffffffu, o[8][0], lane & 28);
    const float den1 = __shfl_sync(0xffffffffu, o[8][2], lane & 28);

    const int r0 = q0w + g, r1 = q0w + g + 8;
    float* msh = (float*)(smem + OFF_MSH);
    float* dsh = (float*)(smem + OFF_DSH);
    if (u == 0) {
        msh[half * 128 + r0] = mrow0;  msh[half * 128 + r1] = mrow1;
        dsh[half * 128 + r0] = den0;   dsh[half * 128 + r1] = den1;
    }
    __syncthreads();

    const float g0 = gamma[0];
    const float mo0 = msh[(1 - half) * 128 + r0], do0 = dsh[(1 - half) * 128 + r0];
    const float mo1 = msh[(1 - half) * 128 + r1], do1 = dsh[(1 - half) * 128 + r1];
    const float mf0 = fmaxf(mrow0, mo0), mf1 = fmaxf(mrow1, mo1);
    const float sm0 = ex2f(mrow0 - mf0), sm1 = ex2f(mrow1 - mf1);
    const float df0 = den0 * sm0 + do0 * ex2f(mo0 - mf0);
    const float df1 = den1 * sm1 + do1 * ex2f(mo1 - mf1);
    const float inv0 = g0 * sm0 / df0, inv1 = g0 * sm1 / df1;

    float* Ost = (float*)(smem + (half ? OFF_OST1 : OFF_OST0));
    #pragma unroll
    for (int ct = 0; ct < 8; ct++) {
        const int c = ct * 8 + 2 * u;
        Ost[c * 128 + r0]       = o[ct][0] * inv0;
        Ost[(c + 1) * 128 + r0] = o[ct][1] * inv0;
        Ost[c * 128 + r1]       = o[ct][2] * inv1;
        Ost[(c + 1) * 128 + r1] = o[ct][3] * inv1;
    }
    __syncthreads();

    const float* O0 = (const float*)(smem + OFF_OST0);
    const float* O1 = (const float*)(smem + OFF_OST1);
    for (int e = tid; e < 2048; e += 512) {
        const int c = e >> 5, q4 = (e & 31) * 4;
        const int idx = c * 128 + q4;
        float4 a = *(const float4*)&O0[idx];
        const float4 bb = *(const float4*)&O1[idx];
        const size_t off = (size_t)(b * 64 + c) * HW + n0 + q4;
        const float4 xv = *(const float4*)&x[off];
        a.x += bb.x + xv.x; a.y += bb.y + xv.y;
        a.z += bb.z + xv.z; a.w += bb.w + xv.w;
        *(float4*)&out[off] = a;
    }
}

// ================= launch =================
extern "C" void kernel_launch(void* const* d_in, const int* in_sizes, int n_in,
                              void* d_out, int out_size)
{
    (void)in_sizes; (void)n_in; (void)out_size;
    const float* x       = (const float*)d_in[0];
    const float* Wq      = (const float*)d_in[1];
    const float* bq      = (const float*)d_in[2];
    const float* Wk      = (const float*)d_in[3];
    const float* bk      = (const float*)d_in[4];
    const float* Wv      = (const float*)d_in[5];
    const float* bv      = (const float*)d_in[6];
    const float* We1     = (const float*)d_in[7];
    const float* be1     = (const float*)d_in[8];
    const float* bn_w    = (const float*)d_in[9];
    const float* bn_b    = (const float*)d_in[10];
    const float* bn_mean = (const float*)d_in[11];
    const float* bn_var  = (const float*)d_in[12];
    const float* We2     = (const float*)d_in[13];
    const float* be2     = (const float*)d_in[14];
    const float* gamma   = (const float*)d_in[15];
    const float* beta    = (const float*)d_in[16];
    float* out = (float*)d_out;

    cudaFuncSetAttribute(edge_kernel, cudaFuncAttributeMaxDynamicSharedMemorySize,
                         EDGE_SMEM);
    edge_kernel<<<dim3(32, NB), 512, EDGE_SMEM>>>(x, We1, be1, bn_w, bn_b,
                                                  bn_mean, bn_var, We2, be2, beta);
    qkv_kernel<<<dim3(32, NB), 384>>>(x, Wq, bq, Wk, bk, Wv, bv);

    cudaFuncSetAttribute(flash_kernel, cudaFuncAttributeMaxDynamicSharedMemorySize,
                         SMEM_BYTES);
    flash_kernel<<<dim3(32, NB), 512, SMEM_BYTES>>>(x, gamma, out);
}

// round 16
// speedup vs baseline: 1.6215x; 1.2812x over previous
#include <cuda_runtime.h>
#include <cuda_fp16.h>
#include <cstdint>

#define HW    4096
#define NB    4
#define LOG2E 1.44269504088896340736f

// ---------------- scratch (device globals: allocation-free) ----------------
__device__ __half g_Qf[NB * HW * 64];   // [b][n][c] fp16, pre-scaled by log2e
__device__ __half g_Kf[NB * HW * 64];   // [b][n][c] fp16
__device__ __half g_Vf[NB * 64 * HW];   // [b][c][m] fp16 (w folded in)
__device__ float  g_w [NB * HW];        // w[m] = 1 + beta*edge
__device__ __half g_wh[NB * HW];        // |w| fp16 (for flash den row)

// ---------------- helpers ----------------
__device__ __forceinline__ float ex2f(float x) {
    float r; asm("ex2.approx.f32 %0, %1;" : "=f"(r) : "f"(x)); return r;
}
__device__ __forceinline__ uint32_t f16x2_pack(float lo, float hi) {
    uint32_t r; asm("cvt.rn.f16x2.f32 %0, %1, %2;" : "=r"(r) : "f"(hi), "f"(lo));
    return r;
}
__device__ __forceinline__ uint32_t ex2_h2(uint32_t h2) {
    asm("ex2.approx.f16x2 %0, %0;" : "+r"(h2));
    return h2;
}
__device__ __forceinline__ uint32_t movm_trans(uint32_t a) {
    uint32_t d;
    asm("movmatrix.sync.aligned.m8n8.trans.b16 %0, %1;" : "=r"(d) : "r"(a));
    return d;
}
__device__ __forceinline__ uint32_t smem_u32(const void* p) {
    uint32_t a;
    asm("{ .reg .u64 t; cvta.to.shared.u64 t, %1; cvt.u32.u64 %0, t; }"
        : "=r"(a) : "l"(p));
    return a;
}

#define SW128(o) ((o) ^ (((o) >> 3) & 0x70))
#define SWX(o)   ((o) ^ (((o) >> 4) & 0x70))

// ---------------- cp.async ----------------
#define CP16(dst, src) \
    asm volatile("cp.async.cg.shared.global [%0], [%1], 16;" \
        :: "r"(dst), "l"(src) : "memory")
#define CP_COMMIT() asm volatile("cp.async.commit_group;" ::: "memory")
#define CP_WAIT0()  asm volatile("cp.async.wait_group 0;" ::: "memory")

// ---------------- mma.sync / ldmatrix (fp16) ----------------
#define LDMX4(r, addr) \
    asm volatile("ldmatrix.sync.aligned.m8n8.x4.shared.b16 {%0,%1,%2,%3}, [%4];" \
        : "=r"((r)[0]), "=r"((r)[1]), "=r"((r)[2]), "=r"((r)[3]) : "r"(addr))

#define LDMX4T(r, addr) \
    asm volatile("ldmatrix.sync.aligned.m8n8.x4.trans.shared.b16 {%0,%1,%2,%3}, [%4];" \
        : "=r"((r)[0]), "=r"((r)[1]), "=r"((r)[2]), "=r"((r)[3]) : "r"(addr))

#define MMA16816(d, a, b0, b1) \
    asm volatile("mma.sync.aligned.m16n8k16.row.col.f32.f16.f16.f32 " \
        "{%0,%1,%2,%3},{%4,%5,%6,%7},{%8,%9},{%0,%1,%2,%3};" \
        : "+f"((d)[0]), "+f"((d)[1]), "+f"((d)[2]), "+f"((d)[3]) \
        : "r"((a)[0]), "r"((a)[1]), "r"((a)[2]), "r"((a)[3]), "r"(b0), "r"(b1))

// ================= kernel 1: edge detector via HMMA (R15 proven) ==========
#define EW_BYTES (9 * 32 * 128)
#define EX_BYTES (264 * 128)
#define E_RED    (EW_BYTES + EX_BYTES)
#define EDGE_SMEM (E_RED + 128 * 4)

__global__ __launch_bounds__(512) void edge_kernel(
    const float* __restrict__ x,  const float* __restrict__ We1,
    const float* __restrict__ be1,
    const float* __restrict__ bn_w, const float* __restrict__ bn_b,
    const float* __restrict__ bn_mean, const float* __restrict__ bn_var,
    const float* __restrict__ We2, const float* __restrict__ be2,
    const float* __restrict__ beta)
{
    extern __shared__ char esm[];
    const uint32_t w_b = smem_u32(esm);
    const uint32_t x_b = w_b + EW_BYTES;
    float* red = (float*)(esm + E_RED);
    __shared__ float s_sc[32], s_sh[32], s_w2[32];

    const int tid = threadIdx.x;
    const int b   = blockIdx.y;
    const int pr0 = blockIdx.x * 2;

    if (tid < 32) {
        float s = bn_w[tid] * rsqrtf(bn_var[tid] + 1e-5f);
        s_sc[tid] = s;
        s_sh[tid] = (be1[tid] - bn_mean[tid]) * s + bn_b[tid];
        s_w2[tid] = We2[tid];
    }

    for (int e = tid; e < 18432; e += 512) {
        const int oc = e / 576, rest = e % 576;
        const int ci = rest / 9, k = rest % 9;
        *(__half*)(esm + k * 4096 + SW128(oc * 128 + ci * 2)) =
            __float2half(We1[e]);
    }
    for (int e = tid; e < 2112; e += 512) {
        const int pos = e >> 3, grp = e & 7;
        const int rr = pos / 66, cc = pos % 66;
        const int ir = pr0 - 1 + rr, ic = cc - 1;
        __half hv[8];
        if (ir >= 0 && ir < 64 && ic >= 0 && ic < 64) {
            const float* xp = x + (size_t)(b * 64 + grp * 8) * HW + ir * 64 + ic;
            #pragma unroll
            for (int i = 0; i < 8; i++) hv[i] = __float2half(xp[(size_t)i * HW]);
        } else {
            #pragma unroll
            for (int i = 0; i < 8; i++) hv[i] = __half(0.f);
        }
        *(uint4*)(esm + EW_BYTES + SW128(pos * 128 + grp * 16)) = *(uint4*)hv;
    }
    __syncthreads();

    const int wid = tid >> 5, lane = tid & 31;
    const int g   = lane >> 2, u = lane & 3;
    const int m   = wid >> 3;
    const int t8  = wid & 7;
    const int oc_b = m * 16;
    const int tr  = t8 >> 2;
    const int tcb = (t8 & 3) * 16;

    float s[2][4];
    s[0][0]=s[0][1]=s[0][2]=s[0][3]=0.f;
    s[1][0]=s[1][1]=s[1][2]=s[1][3]=0.f;

    #pragma unroll
    for (int tap = 0; tap < 9; tap++) {
        const int dy = tap / 3 - 1, dx = tap % 3 - 1;
        uint32_t aW[4][4];
        #pragma unroll
        for (int ks = 0; ks < 4; ks++)
            LDMX4(aW[ks], w_b + tap * 4096 +
                  SW128((oc_b + (lane & 15)) * 128 + ks * 32 + (lane >> 4) * 16));
        const int pbase = (tr + 1 + dy) * 66 + tcb + 1 + dx;
        #pragma unroll
        for (int nt = 0; nt < 2; nt++) {
            uint32_t bh[8];
            const uint32_t ro = (pbase + nt * 8 + (lane & 7)) * 128 +
                                (lane >> 3) * 16;
            LDMX4(bh,     x_b + SW128(ro));
            LDMX4(bh + 4, x_b + SW128(ro + 64));
            #pragma unroll
            for (int ks = 0; ks < 4; ks++)
                MMA16816(s[nt], aW[ks], bh[2 * ks], bh[2 * ks + 1]);
        }
    }

    const float sc0 = s_sc[oc_b + g],     sh0 = s_sh[oc_b + g];
    const float sc1 = s_sc[oc_b + 8 + g], sh1 = s_sh[oc_b + 8 + g];
    const float w20 = s_w2[oc_b + g],     w21 = s_w2[oc_b + 8 + g];
    float part[2][2];
    #pragma unroll
    for (int nt = 0; nt < 2; nt++) {
        const float r00 = fmaxf(s[nt][0] * sc0 + sh0, 0.f);
        const float r01 = fmaxf(s[nt][1] * sc0 + sh0, 0.f);
        const float r10 = fmaxf(s[nt][2] * sc1 + sh1, 0.f);
        const float r11 = fmaxf(s[nt][3] * sc1 + sh1, 0.f);
        part[nt][0] = w20 * r00 + w21 * r10;
        part[nt][1] = w20 * r01 + w21 * r11;
        #pragma unroll
        for (int off = 16; off >= 4; off >>= 1) {
            part[nt][0] += __shfl_xor_sync(0xffffffffu, part[nt][0], off);
            part[nt][1] += __shfl_xor_sync(0xffffffffu, part[nt][1], off);
        }
    }

    if (m == 1 && g == 0) {
        #pragma unroll
        for (int nt = 0; nt < 2; nt++) {
            red[t8 * 16 + nt * 8 + 2 * u]     = part[nt][0];
            red[t8 * 16 + nt * 8 + 2 * u + 1] = part[nt][1];
        }
    }
    __syncthreads();
    if (m == 0 && g == 0) {
        const float bb2 = be2[0], bt = beta[0];
        #pragma unroll
        for (int nt = 0; nt < 2; nt++) {
            #pragma unroll
            for (int c = 0; c < 2; c++) {
                const int tok = t8 * 16 + nt * 8 + 2 * u + c;
                const float e2 = bb2 + part[nt][c] + red[tok];
                const float sig = 1.f / (1.f + ex2f(-e2 * LOG2E));
                const float wv = 1.f + bt * sig;
                g_w [b * HW + pr0 * 64 + tok] = wv;
                g_wh[b * HW + pr0 * 64 + tok] = __float2half(fabsf(wv));
            }
        }
    }
}

// ================= kernel 2: QKV via HMMA (R12 proven) =================
__global__ __launch_bounds__(384) void qkv_kernel(
    const float* __restrict__ x,
    const float* __restrict__ Wq, const float* __restrict__ bq,
    const float* __restrict__ Wk, const float* __restrict__ bk,
    const float* __restrict__ Wv, const float* __restrict__ bv)
{
    __shared__ __align__(16) __half Wf[192 * 64];
    __shared__ __align__(16) __half xB[64 * 128];
    __shared__ float sb[192];
    __shared__ float wvs[128];

    const int tid = threadIdx.x;
    const int b   = blockIdx.y;
    const int n0  = blockIdx.x * 128;
    const uint32_t wf_b = smem_u32(Wf);
    const uint32_t xb_b = smem_u32(xB);

    for (int e = tid; e < 1536; e += 384) {
        int oc = e >> 3, chv = e & 7;
        const float* wsrc;
        float scale = 1.f;
        if (oc < 64)       { wsrc = Wq + oc * 64;        scale = LOG2E; }
        else if (oc < 128) { wsrc = Wk + (oc - 64) * 64; }
        else               { wsrc = Wv + (oc - 128) * 64; }
        const float4 f0 = *(const float4*)(wsrc + chv * 8);
        const float4 f1 = *(const float4*)(wsrc + chv * 8 + 4);
        __half2 h[4];
        h[0] = __floats2half2_rn(f0.x * scale, f0.y * scale);
        h[1] = __floats2half2_rn(f0.z * scale, f0.w * scale);
        h[2] = __floats2half2_rn(f1.x * scale, f1.y * scale);
        h[3] = __floats2half2_rn(f1.z * scale, f1.w * scale);
        *(uint4*)((char*)Wf + SW128(oc * 128 + chv * 16)) = *(uint4*)h;
    }
    for (int e = tid; e < 1024; e += 384) {
        int c = e >> 4, ch = e & 15;
        const float* xp = x + (size_t)(b * 64 + c) * HW + n0 + ch * 8;
        const float4 f0 = *(const float4*)xp;
        const float4 f1 = *(const float4*)(xp + 4);
        __half2 h[4];
        h[0] = __floats2half2_rn(f0.x, f0.y);
        h[1] = __floats2half2_rn(f0.z, f0.w);
        h[2] = __floats2half2_rn(f1.x, f1.y);
        h[3] = __floats2half2_rn(f1.z, f1.w);
        *(uint4*)((char*)xB + SWX(c * 256 + ch * 16)) = *(uint4*)h;
    }
    if (tid < 192)
        sb[tid] = (tid < 64) ? bq[tid] * LOG2E
                 : (tid < 128) ? bk[tid - 64] : bv[tid - 128];
    if (tid < 128) wvs[tid] = g_w[b * HW + n0 + tid];
    __syncthreads();

    const int wid  = tid >> 5, lane = tid & 31;
    const int g    = lane >> 2, u = lane & 3;
    const int mt   = wid;
    const int oc_b = mt * 16;

    uint32_t aW[4][4];
    #pragma unroll
    for (int ks = 0; ks < 4; ks++)
        LDMX4(aW[ks], wf_b + SW128((oc_b + (lane & 15)) * 128 +
                                   ks * 32 + (lane >> 4) * 16));

    float s[16][4];
    #pragma unroll
    for (int i = 0; i < 16; i++)
        s[i][0] = s[i][1] = s[i][2] = s[i][3] = 0.f;

    #pragma unroll
    for (int nt2 = 0; nt2 < 8; nt2++) {
        #pragma unroll
        for (int ks = 0; ks < 4; ks++) {
            uint32_t bb[4];
            LDMX4T(bb, xb_b + SWX((ks * 16 + (lane & 15)) * 256 +
                                  nt2 * 32 + (lane >> 4) * 16));
            MMA16816(s[2 * nt2],     aW[ks], bb[0], bb[1]);
            MMA16816(s[2 * nt2 + 1], aW[ks], bb[2], bb[3]);
        }
    }

    const float b0 = sb[oc_b + g], b1 = sb[oc_b + 8 + g];
    const bool isV = (mt >= 8);
    #pragma unroll
    for (int nt = 0; nt < 16; nt++) {
        const int nn = nt * 8 + 2 * u;
        float v00 = s[nt][0] + b0, v01 = s[nt][1] + b0;
        float v10 = s[nt][2] + b1, v11 = s[nt][3] + b1;
        if (isV) {
            const float w0 = wvs[nn], w1 = wvs[nn + 1];
            v00 *= w0; v01 *= w1; v10 *= w0; v11 *= w1;
        }
        uint32_t h0 = f16x2_pack(v00, v01);
        uint32_t h1 = f16x2_pack(v10, v11);
        if (isV) {
            const size_t vb = (size_t)(b * 64 + (oc_b - 128) + g) * HW + n0 + nn;
            *(uint32_t*)(g_Vf + vb)          = h0;
            *(uint32_t*)(g_Vf + vb + 8 * HW) = h1;
        } else {
            uint32_t t0 = movm_trans(h0);
            uint32_t t1 = movm_trans(h1);
            const int n = nt * 8 + g;
            __half* dst = (mt < 4) ? g_Qf : g_Kf;
            const int cb = (mt < 4) ? oc_b : oc_b - 64;
            const size_t qb = (size_t)(b * HW + n0 + n) * 64 + cb + 2 * u;
            *(uint32_t*)(dst + qb)     = t0;
            *(uint32_t*)(dst + qb + 8) = t1;
        }
    }
}

// ================= kernel 3: fp16 flash, cp.async tile loads ==============
#define OFF_QF 0            // 16KB
#define OFF_K  16384        // 2 bufs * 16KB
#define VHALF  9216         // 72 rows * 128B
#define VBUF   (2 * VHALF)
#define OFF_V  49152        // 2 bufs * VBUF
#define SMEM_BYTES 86400
#define OFF_OST0 0
#define OFF_OST1 32768
#define OFF_MSH  65536
#define OFF_DSH  66560

__global__ __launch_bounds__(512, 1) void flash_kernel(
    const float* __restrict__ x, const float* __restrict__ gamma,
    float* __restrict__ out)
{
    extern __shared__ char smem[];
    const uint32_t sbase = smem_u32(smem);
    const int tid  = threadIdx.x;
    const int lane = tid & 31, wid = tid >> 5;
    const int qg   = wid & 7;
    const int half = wid >> 3;
    const int g    = lane >> 2;
    const int u    = lane & 3;
    const int q0w  = qg * 16;
    const int b    = blockIdx.y;
    const int n0   = blockIdx.x * 128;

    {
        const uint4* Qg = (const uint4*)(g_Qf + ((size_t)(b * HW + n0)) * 64);
        const uint4* Kg = (const uint4*)(g_Kf + ((size_t)(b * HW)) * 64);
        for (int e = tid; e < 1024; e += 512) {
            int r = e >> 3, c8 = e & 7;
            uint32_t o = SW128(r * 128 + c8 * 16);
            *(uint4*)(smem + OFF_QF + o) = Qg[e];
            *(uint4*)(smem + OFF_K + o)  = Kg[e];
        }
        const __half* Vg = g_Vf + (size_t)b * 64 * HW;
        for (int e = tid; e < 1024; e += 512) {
            int c = e >> 4, j8 = e & 15;
            uint4 val = *(const uint4*)(Vg + (size_t)c * HW + j8 * 8);
            *(uint4*)(smem + OFF_V + (j8 >> 3) * VHALF +
                      SW128(c * 128 + (j8 & 7) * 16)) = val;
        }
        const uint4 zz = make_uint4(0, 0, 0, 0);
        for (int e = tid; e < 224; e += 512) {
            int buf = e / 112, rest = e % 112;
            int h = rest / 56, r = rest % 56;
            int row = 65 + r / 8, c16 = r % 8;
            *(uint4*)(smem + OFF_V + buf * VBUF + h * VHALF +
                      SW128(row * 128 + c16 * 16)) = zz;
        }
        if (tid < 16) {
            int h = tid >> 3, grp = tid & 7;
            *(uint4*)(smem + OFF_V + h * VHALF + SW128(64 * 128 + grp * 16)) =
                *(const uint4*)(g_wh + b * HW + h * 64 + grp * 8);
        }
    }
    __syncthreads();

    float o[9][4];
    #pragma unroll
    for (int ct = 0; ct < 9; ct++)
        o[ct][0] = o[ct][1] = o[ct][2] = o[ct][3] = 0.f;
    float mrow0 = -1e30f, mrow1 = -1e30f;

    const int qrow = q0w + (lane & 15);

    for (int t = 0; t < 32; t++) {
        const int buf = t & 1;

        // ---- async prefetch of tile t+1 (issue-and-forget) ----
        if (t < 31) {
            const int m1 = (t + 1) * 128, nb = buf ^ 1;
            const char* Kg = (const char*)(g_Kf + ((size_t)(b * HW + m1)) * 64);
            const uint32_t kb = sbase + OFF_K + nb * 16384;
            for (int e = tid; e < 1024; e += 512) {
                int r = e >> 3, c8 = e & 7;
                CP16(kb + SW128(r * 128 + c8 * 16), Kg + e * 16);
            }
            const char* Vg = (const char*)(g_Vf + (size_t)b * 64 * HW + m1);
            const uint32_t vb = sbase + OFF_V + nb * VBUF;
            for (int e = tid; e < 1024; e += 512) {
                int c = e >> 4, j8 = e & 15;
                CP16(vb + (j8 >> 3) * VHALF + SW128(c * 128 + (j8 & 7) * 16),
                     Vg + ((size_t)c * HW + j8 * 8) * 2);
            }
            if (tid < 16) {
                int h = tid >> 3, grp = tid & 7;
                CP16(vb + h * VHALF + SW128(64 * 128 + grp * 16),
                     (const char*)(g_wh + b * HW + m1 + h * 64 + grp * 8));
            }
            CP_COMMIT();
        }

        const uint32_t k_b = sbase + OFF_K + buf * 16384;

        // ---- reload Q fragments (short live range) ----
        uint32_t qf[4][4];
        #pragma unroll
        for (int ks = 0; ks < 4; ks++) {
            const uint32_t cb = ks * 32 + (lane >> 4) * 16;
            LDMX4(qf[ks], sbase + OFF_QF + SW128(qrow * 128 + cb));
        }

        // ---- S = QK^T for this warp's 64 keys ----
        float s[8][4];
        #pragma unroll
        for (int i = 0; i < 8; i++)
            s[i][0] = s[i][1] = s[i][2] = s[i][3] = 0.f;

        #pragma unroll
        for (int i = 0; i < 8; i++) {
            const int nt = half * 8 + i;
            const uint32_t roff = (nt * 8 + (lane & 7)) * 128 + (lane >> 3) * 16;
            uint32_t bh[8];
            LDMX4(bh,     k_b + SW128(roff));
            LDMX4(bh + 4, k_b + SW128(roff + 64));
            #pragma unroll
            for (int ks = 0; ks < 4; ks++)
                MMA16816(s[i], qf[ks], bh[2 * ks], bh[2 * ks + 1]);
        }

        // ---- online max (quad-local) ----
        float mx0 = s[0][0], mx1 = s[0][2];
        #pragma unroll
        for (int i = 0; i < 8; i++) {
            mx0 = fmaxf(mx0, fmaxf(s[i][0], s[i][1]));
            mx1 = fmaxf(mx1, fmaxf(s[i][2], s[i][3]));
        }
        mx0 = fmaxf(mx0, __shfl_xor_sync(0xffffffffu, mx0, 1));
        mx0 = fmaxf(mx0, __shfl_xor_sync(0xffffffffu, mx0, 2));
        mx1 = fmaxf(mx1, __shfl_xor_sync(0xffffffffu, mx1, 1));
        mx1 = fmaxf(mx1, __shfl_xor_sync(0xffffffffu, mx1, 2));

        const float mn0 = fmaxf(mrow0, mx0), mn1 = fmaxf(mrow1, mx1);
        const float cr0 = ex2f(mrow0 - mn0), cr1 = ex2f(mrow1 - mn1);
        mrow0 = mn0; mrow1 = mn1;

        // ---- p = exp2(s - mn) directly as fp16x2 A-fragments ----
        uint32_t aP[4][4];
        #pragma unroll
        for (int i = 0; i < 8; i++) {
            aP[i >> 1][(i & 1) * 2] =
                ex2_h2(f16x2_pack(s[i][0] - mn0, s[i][1] - mn0));
            aP[i >> 1][(i & 1) * 2 + 1] =
                ex2_h2(f16x2_pack(s[i][2] - mn1, s[i][3] - mn1));
        }

        // ---- rescale accumulators (incl. den column) ----
        #pragma unroll
        for (int ct = 0; ct < 9; ct++) {
            o[ct][0] *= cr0; o[ct][1] *= cr0;
            o[ct][2] *= cr1; o[ct][3] *= cr1;
        }

        // ---- O += P * [Vw | |w|] ----
        const uint32_t v_b = sbase + OFF_V + buf * VBUF + half * VHALF;
        #pragma unroll
        for (int ct = 0; ct < 9; ct++) {
            const uint32_t roff = (ct * 8 + (lane & 7)) * 128 + (lane >> 3) * 16;
            uint32_t vb[8];
            LDMX4(vb,     v_b + SW128(roff));
            LDMX4(vb + 4, v_b + SW128(roff + 64));
            #pragma unroll
            for (int j = 0; j < 4; j++)
                MMA16816(o[ct], aP[j], vb[2 * j], vb[2 * j + 1]);
        }

        if (t < 31) CP_WAIT0();
        __syncthreads();
    }

    const float den0 = __shfl_sync(0xffffffffu, o[8][0], lane & 28);
    const float den1 = __shfl_sync(0xffffffffu, o[8][2], lane & 28);

    const int r0 = q0w + g, r1 = q0w + g + 8;
    float* msh = (float*)(smem + OFF_MSH);
    float* dsh = (float*)(smem + OFF_DSH);
    if (u == 0) {
        msh[half * 128 + r0] = mrow0;  msh[half * 128 + r1] = mrow1;
        dsh[half * 128 + r0] = den0;   dsh[half * 128 + r1] = den1;
    }
    __syncthreads();

    const float g0 = gamma[0];
    const float mo0 = msh[(1 - half) * 128 + r0], do0 = dsh[(1 - half) * 128 + r0];
    const float mo1 = msh[(1 - half) * 128 + r1], do1 = dsh[(1 - half) * 128 + r1];
    const float mf0 = fmaxf(mrow0, mo0), mf1 = fmaxf(mrow1, mo1);
    const float sm0 = ex2f(mrow0 - mf0), sm1 = ex2f(mrow1 - mf1);
    const float df0 = den0 * sm0 + do0 * ex2f(mo0 - mf0);
    const float df1 = den1 * sm1 + do1 * ex2f(mo1 - mf1);
    const float inv0 = g0 * sm0 / df0, inv1 = g0 * sm1 / df1;

    float* Ost = (float*)(smem + (half ? OFF_OST1 : OFF_OST0));
    #pragma unroll
    for (int ct = 0; ct < 8; ct++) {
        const int c = ct * 8 + 2 * u;
        Ost[c * 128 + r0]       = o[ct][0] * inv0;
        Ost[(c + 1) * 128 + r0] = o[ct][1] * inv0;
        Ost[c * 128 + r1]       = o[ct][2] * inv1;
        Ost[(c + 1) * 128 + r1] = o[ct][3] * inv1;
    }
    __syncthreads();

    const float* O0 = (const float*)(smem + OFF_OST0);
    const float* O1 = (const float*)(smem + OFF_OST1);
    for (int e = tid; e < 2048; e += 512) {
        const int c = e >> 5, q4 = (e & 31) * 4;
        const int idx = c * 128 + q4;
        float4 a = *(const float4*)&O0[idx];
        const float4 bb = *(const float4*)&O1[idx];
        const size_t off = (size_t)(b * 64 + c) * HW + n0 + q4;
        const float4 xv = *(const float4*)&x[off];
        a.x += bb.x + xv.x; a.y += bb.y + xv.y;
        a.z += bb.z + xv.z; a.w += bb.w + xv.w;
        *(float4*)&out[off] = a;
    }
}

// ================= launch =================
extern "C" void kernel_launch(void* const* d_in, const int* in_sizes, int n_in,
                              void* d_out, int out_size)
{
    (void)in_sizes; (void)n_in; (void)out_size;
    const float* x       = (const float*)d_in[0];
    const float* Wq      = (const float*)d_in[1];
    const float* bq      = (const float*)d_in[2];
    const float* Wk      = (const float*)d_in[3];
    const float* bk      = (const float*)d_in[4];
    const float* Wv      = (const float*)d_in[5];
    const float* bv      = (const float*)d_in[6];
    const float* We1     = (const float*)d_in[7];
    const float* be1     = (const float*)d_in[8];
    const float* bn_w    = (const float*)d_in[9];
    const float* bn_b    = (const float*)d_in[10];
    const float* bn_mean = (const float*)d_in[11];
    const float* bn_var  = (const float*)d_in[12];
    const float* We2     = (const float*)d_in[13];
    const float* be2     = (const float*)d_in[14];
    const float* gamma   = (const float*)d_in[15];
    const float* beta    = (const float*)d_in[16];
    float* out = (float*)d_out;

    cudaFuncSetAttribute(edge_kernel, cudaFuncAttributeMaxDynamicSharedMemorySize,
                         EDGE_SMEM);
    edge_kernel<<<dim3(32, NB), 512, EDGE_SMEM>>>(x, We1, be1, bn_w, bn_b,
                                                  bn_mean, bn_var, We2, be2, beta);
    qkv_kernel<<<dim3(32, NB), 384>>>(x, Wq, bq, Wk, bk, Wv, bv);

    cudaFuncSetAttribute(flash_kernel, cudaFuncAttributeMaxDynamicSharedMemorySize,
                         SMEM_BYTES);
    flash_kernel<<<dim3(32, NB), 512, SMEM_BYTES>>>(x, gamma, out);
}

// round 17
// speedup vs baseline: 1.7334x; 1.0690x over previous
#include <cuda_runtime.h>
#include <cuda_fp16.h>
#include <cstdint>

#define HW    4096
#define NB    4
#define LOG2E 1.44269504088896340736f

// ---------------- scratch (device globals: allocation-free) ----------------
__device__ __half g_Qf[NB * HW * 64];   // [b][n][c] fp16, pre-scaled by log2e
__device__ __half g_Kf[NB * HW * 64];   // [b][n][c] fp16
__device__ __half g_Vf[NB * 64 * HW];   // [b][c][m] fp16 (w folded in)
__device__ __half g_wh[NB * HW];        // |w| fp16 (flash den row)

// ---------------- helpers ----------------
__device__ __forceinline__ float ex2f(float x) {
    float r; asm("ex2.approx.f32 %0, %1;" : "=f"(r) : "f"(x)); return r;
}
__device__ __forceinline__ uint32_t f16x2_pack(float lo, float hi) {
    uint32_t r; asm("cvt.rn.f16x2.f32 %0, %1, %2;" : "=r"(r) : "f"(hi), "f"(lo));
    return r;
}
__device__ __forceinline__ uint32_t ex2_h2(uint32_t h2) {
    asm("ex2.approx.f16x2 %0, %0;" : "+r"(h2));
    return h2;
}
__device__ __forceinline__ uint32_t movm_trans(uint32_t a) {
    uint32_t d;
    asm("movmatrix.sync.aligned.m8n8.trans.b16 %0, %1;" : "=r"(d) : "r"(a));
    return d;
}
__device__ __forceinline__ uint32_t smem_u32(const void* p) {
    uint32_t a;
    asm("{ .reg .u64 t; cvta.to.shared.u64 t, %1; cvt.u32.u64 %0, t; }"
        : "=r"(a) : "l"(p));
    return a;
}

#define SW128(o) ((o) ^ (((o) >> 3) & 0x70))

// ---------------- cp.async / barriers ----------------
#define CP16(dst, src) \
    asm volatile("cp.async.cg.shared.global [%0], [%1], 16;" \
        :: "r"(dst), "l"(src) : "memory")
#define CP_COMMIT() asm volatile("cp.async.commit_group;" ::: "memory")
#define CP_WAIT0()  asm volatile("cp.async.wait_group 0;" ::: "memory")
#define BARH(id)    asm volatile("bar.sync %0, 256;" :: "r"(id) : "memory")

// ---------------- mma.sync / ldmatrix (fp16) ----------------
#define LDMX4(r, addr) \
    asm volatile("ldmatrix.sync.aligned.m8n8.x4.shared.b16 {%0,%1,%2,%3}, [%4];" \
        : "=r"((r)[0]), "=r"((r)[1]), "=r"((r)[2]), "=r"((r)[3]) : "r"(addr))

#define MMA16816(d, a, b0, b1) \
    asm volatile("mma.sync.aligned.m16n8k16.row.col.f32.f16.f16.f32 " \
        "{%0,%1,%2,%3},{%4,%5,%6,%7},{%8,%9},{%0,%1,%2,%3};" \
        : "+f"((d)[0]), "+f"((d)[1]), "+f"((d)[2]), "+f"((d)[3]) \
        : "r"((a)[0]), "r"((a)[1]), "r"((a)[2]), "r"((a)[3]), "r"(b0), "r"(b1))

// ================= kernel 1: fused edge + QKV =================
// Phase A: 3x3 conv edge detector via 9 shifted HMMA GEMMs -> w (smem + g_wh)
// Phase B: QKV projections via HMMA, B-matrix read from phase A's X tile
//          through ldmatrix row-gather (halo-position mapping).
#define FW_BYTES 36864                 // 9 taps * 32oc * 128B (phase A)
#define FX_OFF   36864                 // X tile: [264 pos][64 ch] fp16 SW128
#define FX_BYTES 33792
#define FRED_OFF (FX_OFF + FX_BYTES)   // 70656, 512B reduction buffer
#define FUSED_SMEM (FRED_OFF + 512)    // 71168
// phase B overlay of region0:
#define QW_OFF  0                      // Wf 192*128B = 24576
#define SB_OFF  24576                  // 192 f32 biases
#define WVS_OFF 25344                  // 128 f32 w values (written by phase A)

__global__ __launch_bounds__(512) void fused_kernel(
    const float* __restrict__ x,
    const float* __restrict__ Wq, const float* __restrict__ bq,
    const float* __restrict__ Wk, const float* __restrict__ bk,
    const float* __restrict__ Wv, const float* __restrict__ bv,
    const float* __restrict__ We1, const float* __restrict__ be1,
    const float* __restrict__ bn_w, const float* __restrict__ bn_b,
    const float* __restrict__ bn_mean, const float* __restrict__ bn_var,
    const float* __restrict__ We2, const float* __restrict__ be2,
    const float* __restrict__ beta)
{
    extern __shared__ char esm[];
    const uint32_t r0_b = smem_u32(esm);
    const uint32_t x_b  = r0_b + FX_OFF;
    float* red = (float*)(esm + FRED_OFF);
    float* wvs = (float*)(esm + WVS_OFF);
    float* sb  = (float*)(esm + SB_OFF);
    __shared__ float s_sc[32], s_sh[32], s_w2[32];

    const int tid = threadIdx.x;
    const int b   = blockIdx.y;
    const int pr0 = blockIdx.x * 2;          // image row base
    const int n0  = blockIdx.x * 128;        // token base

    if (tid < 32) {
        float s = bn_w[tid] * rsqrtf(bn_var[tid] + 1e-5f);
        s_sc[tid] = s;
        s_sh[tid] = (be1[tid] - bn_mean[tid]) * s + bn_b[tid];
        s_w2[tid] = We2[tid];
    }

    // ---- phase A fills ----
    for (int e = tid; e < 18432; e += 512) {
        const int oc = e / 576, rest = e % 576;
        const int ci = rest / 9, k = rest % 9;
        *(__half*)(esm + k * 4096 + SW128(oc * 128 + ci * 2)) =
            __float2half(We1[e]);
    }
    for (int e = tid; e < 2112; e += 512) {
        const int pos = e >> 3, grp = e & 7;
        const int rr = pos / 66, cc = pos % 66;
        const int ir = pr0 - 1 + rr, ic = cc - 1;
        __half hv[8];
        if (ir >= 0 && ir < 64 && ic >= 0 && ic < 64) {
            const float* xp = x + (size_t)(b * 64 + grp * 8) * HW + ir * 64 + ic;
            #pragma unroll
            for (int i = 0; i < 8; i++) hv[i] = __float2half(xp[(size_t)i * HW]);
        } else {
            #pragma unroll
            for (int i = 0; i < 8; i++) hv[i] = __half(0.f);
        }
        *(uint4*)(esm + FX_OFF + SW128(pos * 128 + grp * 16)) = *(uint4*)hv;
    }
    __syncthreads();

    const int wid = tid >> 5, lane = tid & 31;
    const int g   = lane >> 2, u = lane & 3;

    // ---- phase A: edge conv mma ----
    {
        const int m   = wid >> 3;
        const int t8  = wid & 7;
        const int oc_b = m * 16;
        const int tr  = t8 >> 2;
        const int tcb = (t8 & 3) * 16;

        float s[2][4];
        s[0][0]=s[0][1]=s[0][2]=s[0][3]=0.f;
        s[1][0]=s[1][1]=s[1][2]=s[1][3]=0.f;

        #pragma unroll
        for (int tap = 0; tap < 9; tap++) {
            const int dy = tap / 3 - 1, dx = tap % 3 - 1;
            uint32_t aW[4][4];
            #pragma unroll
            for (int ks = 0; ks < 4; ks++)
                LDMX4(aW[ks], r0_b + tap * 4096 +
                      SW128((oc_b + (lane & 15)) * 128 + ks * 32 + (lane >> 4) * 16));
            const int pbase = (tr + 1 + dy) * 66 + tcb + 1 + dx;
            #pragma unroll
            for (int nt = 0; nt < 2; nt++) {
                uint32_t bh[8];
                const uint32_t ro = (pbase + nt * 8 + (lane & 7)) * 128 +
                                    (lane >> 3) * 16;
                LDMX4(bh,     x_b + SW128(ro));
                LDMX4(bh + 4, x_b + SW128(ro + 64));
                #pragma unroll
                for (int ks = 0; ks < 4; ks++)
                    MMA16816(s[nt], aW[ks], bh[2 * ks], bh[2 * ks + 1]);
            }
        }

        const float sc0 = s_sc[oc_b + g],     sh0 = s_sh[oc_b + g];
        const float sc1 = s_sc[oc_b + 8 + g], sh1 = s_sh[oc_b + 8 + g];
        const float w20 = s_w2[oc_b + g],     w21 = s_w2[oc_b + 8 + g];
        float part[2][2];
        #pragma unroll
        for (int nt = 0; nt < 2; nt++) {
            const float r00 = fmaxf(s[nt][0] * sc0 + sh0, 0.f);
            const float r01 = fmaxf(s[nt][1] * sc0 + sh0, 0.f);
            const float r10 = fmaxf(s[nt][2] * sc1 + sh1, 0.f);
            const float r11 = fmaxf(s[nt][3] * sc1 + sh1, 0.f);
            part[nt][0] = w20 * r00 + w21 * r10;
            part[nt][1] = w20 * r01 + w21 * r11;
            #pragma unroll
            for (int off = 16; off >= 4; off >>= 1) {
                part[nt][0] += __shfl_xor_sync(0xffffffffu, part[nt][0], off);
                part[nt][1] += __shfl_xor_sync(0xffffffffu, part[nt][1], off);
            }
        }

        if (m == 1 && g == 0) {
            #pragma unroll
            for (int nt = 0; nt < 2; nt++) {
                red[t8 * 16 + nt * 8 + 2 * u]     = part[nt][0];
                red[t8 * 16 + nt * 8 + 2 * u + 1] = part[nt][1];
            }
        }
        __syncthreads();
        if (m == 0 && g == 0) {
            const float bb2 = be2[0], bt = beta[0];
            #pragma unroll
            for (int nt = 0; nt < 2; nt++) {
                #pragma unroll
                for (int c = 0; c < 2; c++) {
                    const int tok = t8 * 16 + nt * 8 + 2 * u + c;
                    const float e2 = bb2 + part[nt][c] + red[tok];
                    const float sig = 1.f / (1.f + ex2f(-e2 * LOG2E));
                    const float wv = 1.f + bt * sig;
                    wvs[tok] = wv;
                    g_wh[b * HW + n0 + tok] = __float2half(fabsf(wv));
                }
            }
        }
    }
    __syncthreads();

    // ---- phase B fills: Wf (overlays edge taps), sb ----
    for (int e = tid; e < 1536; e += 512) {
        int oc = e >> 3, chv = e & 7;
        const float* wsrc;
        float scale = 1.f;
        if (oc < 64)       { wsrc = Wq + oc * 64;        scale = LOG2E; }
        else if (oc < 128) { wsrc = Wk + (oc - 64) * 64; }
        else               { wsrc = Wv + (oc - 128) * 64; }
        const float4 f0 = *(const float4*)(wsrc + chv * 8);
        const float4 f1 = *(const float4*)(wsrc + chv * 8 + 4);
        __half2 h[4];
        h[0] = __floats2half2_rn(f0.x * scale, f0.y * scale);
        h[1] = __floats2half2_rn(f0.z * scale, f0.w * scale);
        h[2] = __floats2half2_rn(f1.x * scale, f1.y * scale);
        h[3] = __floats2half2_rn(f1.z * scale, f1.w * scale);
        *(uint4*)(esm + QW_OFF + SW128(oc * 128 + chv * 16)) = *(uint4*)h;
    }
    if (tid < 192)
        sb[tid] = (tid < 64) ? bq[tid] * LOG2E
                 : (tid < 128) ? bk[tid - 64] : bv[tid - 128];
    __syncthreads();

    // ---- phase B: QKV mma (12 warps), B from the X tile via row-gather ----
    if (wid < 12) {
        const int mt   = wid;
        const int oc_b = mt * 16;

        uint32_t aW[4][4];
        #pragma unroll
        for (int ks = 0; ks < 4; ks++)
            LDMX4(aW[ks], r0_b + QW_OFF + SW128((oc_b + (lane & 15)) * 128 +
                                                ks * 32 + (lane >> 4) * 16));

        float s[16][4];
        #pragma unroll
        for (int i = 0; i < 16; i++)
            s[i][0] = s[i][1] = s[i][2] = s[i][3] = 0.f;

        #pragma unroll
        for (int nt = 0; nt < 16; nt++) {
            // token = nt*8 + (lane&7); pos = (row+1)*66 + col+1
            const int pos = 66 + (nt >> 3) * 66 + (nt & 7) * 8 + (lane & 7) + 1;
            const uint32_t ro = pos * 128 + (lane >> 3) * 16;
            uint32_t bh[8];
            LDMX4(bh,     x_b + SW128(ro));
            LDMX4(bh + 4, x_b + SW128(ro + 64));
            #pragma unroll
            for (int ks = 0; ks < 4; ks++)
                MMA16816(s[nt], aW[ks], bh[2 * ks], bh[2 * ks + 1]);
        }

        const float b0 = sb[oc_b + g], b1 = sb[oc_b + 8 + g];
        const bool isV = (mt >= 8);
        #pragma unroll
        for (int nt = 0; nt < 16; nt++) {
            const int nn = nt * 8 + 2 * u;
            float v00 = s[nt][0] + b0, v01 = s[nt][1] + b0;
            float v10 = s[nt][2] + b1, v11 = s[nt][3] + b1;
            if (isV) {
                const float w0 = wvs[nn], w1 = wvs[nn + 1];
                v00 *= w0; v01 *= w1; v10 *= w0; v11 *= w1;
            }
            uint32_t h0 = f16x2_pack(v00, v01);
            uint32_t h1 = f16x2_pack(v10, v11);
            if (isV) {
                const size_t vb = (size_t)(b * 64 + (oc_b - 128) + g) * HW + n0 + nn;
                *(uint32_t*)(g_Vf + vb)          = h0;
                *(uint32_t*)(g_Vf + vb + 8 * HW) = h1;
            } else {
                uint32_t t0 = movm_trans(h0);
                uint32_t t1 = movm_trans(h1);
                const int n = nt * 8 + g;
                __half* dst = (mt < 4) ? g_Qf : g_Kf;
                const int cb = (mt < 4) ? oc_b : oc_b - 64;
                const size_t qb = (size_t)(b * HW + n0 + n) * 64 + cb + 2 * u;
                *(uint32_t*)(dst + qb)     = t0;
                *(uint32_t*)(dst + qb + 8) = t1;
            }
        }
    }
}

// ================= kernel 2: fp16 flash, per-half barriers =================
#define OFF_QF 0            // 16KB
#define OFF_K  16384        // 2 bufs * 16KB
#define VHALF  9216         // 72 rows * 128B
#define VBUF   (2 * VHALF)
#define OFF_V  49152        // 2 bufs * VBUF
#define SMEM_BYTES 86400
#define OFF_OST0 0
#define OFF_OST1 32768
#define OFF_MSH  65536
#define OFF_DSH  66560

__global__ __launch_bounds__(512, 1) void flash_kernel(
    const float* __restrict__ x, const float* __restrict__ gamma,
    float* __restrict__ out)
{
    extern __shared__ char smem[];
    const uint32_t sbase = smem_u32(smem);
    const int tid  = threadIdx.x;
    const int lane = tid & 31, wid = tid >> 5;
    const int qg   = wid & 7;
    const int half = wid >> 3;
    const int htid = tid & 255;          // index within half
    const int g    = lane >> 2;
    const int u    = lane & 3;
    const int q0w  = qg * 16;
    const int b    = blockIdx.y;
    const int n0   = blockIdx.x * 128;

    {
        const uint4* Qg = (const uint4*)(g_Qf + ((size_t)(b * HW + n0)) * 64);
        const uint4* Kg = (const uint4*)(g_Kf + ((size_t)(b * HW)) * 64);
        for (int e = tid; e < 1024; e += 512) {
            int r = e >> 3, c8 = e & 7;
            uint32_t o = SW128(r * 128 + c8 * 16);
            *(uint4*)(smem + OFF_QF + o) = Qg[e];
            *(uint4*)(smem + OFF_K + o)  = Kg[e];
        }
        const __half* Vg = g_Vf + (size_t)b * 64 * HW;
        for (int e = tid; e < 1024; e += 512) {
            int c = e >> 4, j8 = e & 15;
            uint4 val = *(const uint4*)(Vg + (size_t)c * HW + j8 * 8);
            *(uint4*)(smem + OFF_V + (j8 >> 3) * VHALF +
                      SW128(c * 128 + (j8 & 7) * 16)) = val;
        }
        const uint4 zz = make_uint4(0, 0, 0, 0);
        for (int e = tid; e < 224; e += 512) {
            int buf = e / 112, rest = e % 112;
            int h = rest / 56, r = rest % 56;
            int row = 65 + r / 8, c16 = r % 8;
            *(uint4*)(smem + OFF_V + buf * VBUF + h * VHALF +
                      SW128(row * 128 + c16 * 16)) = zz;
        }
        if (tid < 16) {
            int h = tid >> 3, grp = tid & 7;
            *(uint4*)(smem + OFF_V + h * VHALF + SW128(64 * 128 + grp * 16)) =
                *(const uint4*)(g_wh + b * HW + h * 64 + grp * 8);
        }
    }
    __syncthreads();

    float o[9][4];
    #pragma unroll
    for (int ct = 0; ct < 9; ct++)
        o[ct][0] = o[ct][1] = o[ct][2] = o[ct][3] = 0.f;
    float mrow0 = -1e30f, mrow1 = -1e30f;

    const int qrow = q0w + (lane & 15);

    for (int t = 0; t < 32; t++) {
        const int buf = t & 1;

        // ---- async prefetch of tile t+1, partitioned by key-half ----
        if (t < 31) {
            const int m1 = (t + 1) * 128, nb = buf ^ 1;
            const char* Kg = (const char*)(g_Kf + ((size_t)(b * HW + m1)) * 64);
            const uint32_t kb = sbase + OFF_K + nb * 16384;
            for (int e = htid; e < 512; e += 256) {
                int r = half * 64 + (e >> 3), c8 = e & 7;
                CP16(kb + SW128(r * 128 + c8 * 16), Kg + r * 128 + c8 * 16);
            }
            const char* Vg = (const char*)(g_Vf + (size_t)b * 64 * HW + m1);
            const uint32_t vb = sbase + OFF_V + nb * VBUF;
            for (int e = htid; e < 512; e += 256) {
                int c = e >> 3, j8 = half * 8 + (e & 7);
                CP16(vb + half * VHALF + SW128(c * 128 + (j8 & 7) * 16),
                     Vg + ((size_t)c * HW + j8 * 8) * 2);
            }
            if (htid < 8) {
                CP16(vb + half * VHALF + SW128(64 * 128 + htid * 16),
                     (const char*)(g_wh + b * HW + m1 + half * 64 + htid * 8));
            }
            CP_COMMIT();
        }

        const uint32_t k_b = sbase + OFF_K + buf * 16384;

        // ---- reload Q fragments (short live range) ----
        uint32_t qf[4][4];
        #pragma unroll
        for (int ks = 0; ks < 4; ks++) {
            const uint32_t cb = ks * 32 + (lane >> 4) * 16;
            LDMX4(qf[ks], sbase + OFF_QF + SW128(qrow * 128 + cb));
        }

        // ---- S = QK^T for this warp's 64 keys ----
        float s[8][4];
        #pragma unroll
        for (int i = 0; i < 8; i++)
            s[i][0] = s[i][1] = s[i][2] = s[i][3] = 0.f;

        #pragma unroll
        for (int i = 0; i < 8; i++) {
            const int nt = half * 8 + i;
            const uint32_t roff = (nt * 8 + (lane & 7)) * 128 + (lane >> 3) * 16;
            uint32_t bh[8];
            LDMX4(bh,     k_b + SW128(roff));
            LDMX4(bh + 4, k_b + SW128(roff + 64));
            #pragma unroll
            for (int ks = 0; ks < 4; ks++)
                MMA16816(s[i], qf[ks], bh[2 * ks], bh[2 * ks + 1]);
        }

        // ---- online max (quad-local) ----
        float mx0 = s[0][0], mx1 = s[0][2];
        #pragma unroll
        for (int i = 0; i < 8; i++) {
            mx0 = fmaxf(mx0, fmaxf(s[i][0], s[i][1]));
            mx1 = fmaxf(mx1, fmaxf(s[i][2], s[i][3]));
        }
        mx0 = fmaxf(mx0, __shfl_xor_sync(0xffffffffu, mx0, 1));
        mx0 = fmaxf(mx0, __shfl_xor_sync(0xffffffffu, mx0, 2));
        mx1 = fmaxf(mx1, __shfl_xor_sync(0xffffffffu, mx1, 1));
        mx1 = fmaxf(mx1, __shfl_xor_sync(0xffffffffu, mx1, 2));

        const float mn0 = fmaxf(mrow0, mx0), mn1 = fmaxf(mrow1, mx1);
        const float cr0 = ex2f(mrow0 - mn0), cr1 = ex2f(mrow1 - mn1);
        mrow0 = mn0; mrow1 = mn1;

        // ---- p = exp2(s - mn) directly as fp16x2 A-fragments ----
        uint32_t aP[4][4];
        #pragma unroll
        for (int i = 0; i < 8; i++) {
            aP[i >> 1][(i & 1) * 2] =
                ex2_h2(f16x2_pack(s[i][0] - mn0, s[i][1] - mn0));
            aP[i >> 1][(i & 1) * 2 + 1] =
                ex2_h2(f16x2_pack(s[i][2] - mn1, s[i][3] - mn1));
        }

        // ---- rescale accumulators (incl. den column) ----
        #pragma unroll
        for (int ct = 0; ct < 9; ct++) {
            o[ct][0] *= cr0; o[ct][1] *= cr0;
            o[ct][2] *= cr1; o[ct][3] *= cr1;
        }

        // ---- O += P * [Vw | |w|] ----
        const uint32_t v_b = sbase + OFF_V + buf * VBUF + half * VHALF;
        #pragma unroll
        for (int ct = 0; ct < 9; ct++) {
            const uint32_t roff = (ct * 8 + (lane & 7)) * 128 + (lane >> 3) * 16;
            uint32_t vb[8];
            LDMX4(vb,     v_b + SW128(roff));
            LDMX4(vb + 4, v_b + SW128(roff + 64));
            #pragma unroll
            for (int j = 0; j < 4; j++)
                MMA16816(o[ct], aP[j], vb[2 * j], vb[2 * j + 1]);
        }

        if (t < 31) {
            CP_WAIT0();
            BARH(1 + half);          // per-half barrier: halves drift/stagger
        }
    }
    __syncthreads();                 // full sync before smem overlay writes

    const float den0 = __shfl_sync(0xffffffffu, o[8][0], lane & 28);
    const float den1 = __shfl_sync(0xffffffffu, o[8][2], lane & 28);

    const int r0 = q0w + g, r1 = q0w + g + 8;
    float* msh = (float*)(smem + OFF_MSH);
    float* dsh = (float*)(smem + OFF_DSH);
    if (u == 0) {
        msh[half * 128 + r0] = mrow0;  msh[half * 128 + r1] = mrow1;
        dsh[half * 128 + r0] = den0;   dsh[half * 128 + r1] = den1;
    }
    __syncthreads();

    const float g0 = gamma[0];
    const float mo0 = msh[(1 - half) * 128 + r0], do0 = dsh[(1 - half) * 128 + r0];
    const float mo1 = msh[(1 - half) * 128 + r1], do1 = dsh[(1 - half) * 128 + r1];
    const float mf0 = fmaxf(mrow0, mo0), mf1 = fmaxf(mrow1, mo1);
    const float sm0 = ex2f(mrow0 - mf0), sm1 = ex2f(mrow1 - mf1);
    const float df0 = den0 * sm0 + do0 * ex2f(mo0 - mf0);
    const float df1 = den1 * sm1 + do1 * ex2f(mo1 - mf1);
    const float inv0 = g0 * sm0 / df0, inv1 = g0 * sm1 / df1;

    float* Ost = (float*)(smem + (half ? OFF_OST1 : OFF_OST0));
    #pragma unroll
    for (int ct = 0; ct < 8; ct++) {
        const int c = ct * 8 + 2 * u;
        Ost[c * 128 + r0]       = o[ct][0] * inv0;
        Ost[(c + 1) * 128 + r0] = o[ct][1] * inv0;
        Ost[c * 128 + r1]       = o[ct][2] * inv1;
        Ost[(c + 1) * 128 + r1] = o[ct][3] * inv1;
    }
    __syncthreads();

    const float* O0 = (const float*)(smem + OFF_OST0);
    const float* O1 = (const float*)(smem + OFF_OST1);
    for (int e = tid; e < 2048; e += 512) {
        const int c = e >> 5, q4 = (e & 31) * 4;
        const int idx = c * 128 + q4;
        float4 a = *(const float4*)&O0[idx];
        const float4 bb = *(const float4*)&O1[idx];
        const size_t off = (size_t)(b * 64 + c) * HW + n0 + q4;
        const float4 xv = *(const float4*)&x[off];
        a.x += bb.x + xv.x; a.y += bb.y + xv.y;
        a.z += bb.z + xv.z; a.w += bb.w + xv.w;
        *(float4*)&out[off] = a;
    }
}

// ================= launch =================
extern "C" void kernel_launch(void* const* d_in, const int* in_sizes, int n_in,
                              void* d_out, int out_size)
{
    (void)in_sizes; (void)n_in; (void)out_size;
    const float* x       = (const float*)d_in[0];
    const float* Wq      = (const float*)d_in[1];
    const float* bq      = (const float*)d_in[2];
    const float* Wk      = (const float*)d_in[3];
    const float* bk      = (const float*)d_in[4];
    const float* Wv      = (const float*)d_in[5];
    const float* bv      = (const float*)d_in[6];
    const float* We1     = (const float*)d_in[7];
    const float* be1     = (const float*)d_in[8];
    const float* bn_w    = (const float*)d_in[9];
    const float* bn_b    = (const float*)d_in[10];
    const float* bn_mean = (const float*)d_in[11];
    const float* bn_var  = (const float*)d_in[12];
    const float* We2     = (const float*)d_in[13];
    const float* be2     = (const float*)d_in[14];
    const float* gamma   = (const float*)d_in[15];
    const float* beta    = (const float*)d_in[16];
    float* out = (float*)d_out;

    cudaFuncSetAttribute(fused_kernel, cudaFuncAttributeMaxDynamicSharedMemorySize,
                         FUSED_SMEM);
    fused_kernel<<<dim3(32, NB), 512, FUSED_SMEM>>>(
        x, Wq, bq, Wk, bk, Wv, bv, We1, be1, bn_w, bn_b, bn_mean, bn_var,
        We2, be2, beta);

    cudaFuncSetAttribute(flash_kernel, cudaFuncAttributeMaxDynamicSharedMemorySize,
                         SMEM_BYTES);
    flash_kernel<<<dim3(32, NB), 512, SMEM_BYTES>>>(x, gamma, out);
}